// round 14
// baseline (speedup 1.0000x reference)
#include <cuda_runtime.h>
#include <cuda_bf16.h>
#include <cuda_fp16.h>
#include <cuda_fp8.h>
#include <math.h>

#define Bv 64
#define Cv 21
#define Pv 96
#define Dv 256
#define Rv 32
#define Hv 64
#define BPv (Bv*Pv)
#define PDv (Pv*Dv)

// padded smem strides (elements); all 16B multiples with odd-16B rotation
#define HB  264   // h_b / wu_b row stride (528B)
#define WB  40    // wd_b row stride (80B)
#define AB  40    // A_b / hl_b row stride (80B)
#define W4B 136   // w4_b row stride (272B)
#define MB  264   // mixed row stride

#define FP8S 32.0f
#define FP8SI (1.0f/32.0f)

// ---------------- device-global precomputed weights -------------------------
__device__ __align__(16) __nv_bfloat16 g_Wdh[Dv*Rv];        // [d][r] = bf16(ln_w*Wd)
__device__ __align__(16) __nv_bfloat16 g_W4h[Rv*128];       // [kk][o]
__device__ __align__(16) __nv_bfloat16 g_Wuh[Rv*Dv];        // [r][d]
__device__ __align__(16) __nv_fp8_storage_t g_dn1f8[Hv*Dv]; // [j][d]
__device__ __align__(16) __nv_fp8_storage_t g_dn2f8[Hv*Dv]; // [j][d]
__device__ float g_SW[Rv];
__device__ float g_LB[Rv];
__device__ float g_logits[Dv];

static __device__ __forceinline__ float geluf(float x) {
    return 0.5f * x * (1.0f + erff(x * 0.70710678118654752f));
}
static __device__ __forceinline__ float gelu_fast(float x) {
    float z = 0.7978845608f * fmaf(0.044715f, x * x * x, x);
    float e = __expf(2.f * z);
    float th = 1.f - __fdividef(2.f, e + 1.f);
    return 0.5f * x * (1.f + th);
}
static __device__ __forceinline__ float sigm(float x) {
    return 1.0f / (1.0f + __expf(-x));
}
static __device__ __forceinline__ __half2 fp8x2_h2(unsigned v) {
    __half2_raw hr = __nv_cvt_fp8x2_to_halfraw2((__nv_fp8x2_storage_t)(v & 0xffffu),
                                                __NV_E4M3);
    return *reinterpret_cast<__half2*>(&hr);
}
static __device__ __forceinline__ unsigned smem_u32(const void* p) {
    return (unsigned)__cvta_generic_to_shared(p);
}
static __device__ __forceinline__ void ldsm_x4(unsigned& r0, unsigned& r1,
                                               unsigned& r2, unsigned& r3, unsigned a) {
    asm volatile("ldmatrix.sync.aligned.m8n8.x4.shared.b16 {%0,%1,%2,%3}, [%4];"
                 : "=r"(r0), "=r"(r1), "=r"(r2), "=r"(r3) : "r"(a));
}
static __device__ __forceinline__ void ldsm_x2t(unsigned& r0, unsigned& r1, unsigned a) {
    asm volatile("ldmatrix.sync.aligned.m8n8.x2.trans.shared.b16 {%0,%1}, [%2];"
                 : "=r"(r0), "=r"(r1) : "r"(a));
}
static __device__ __forceinline__ void mma16816(float& c0, float& c1, float& c2, float& c3,
                                                unsigned a0, unsigned a1, unsigned a2, unsigned a3,
                                                unsigned b0, unsigned b1) {
    asm volatile("mma.sync.aligned.m16n8k16.row.col.f32.bf16.bf16.f32 "
                 "{%0,%1,%2,%3}, {%4,%5,%6,%7}, {%8,%9}, {%0,%1,%2,%3};"
                 : "+f"(c0), "+f"(c1), "+f"(c2), "+f"(c3)
                 : "r"(a0), "r"(a1), "r"(a2), "r"(a3), "r"(b0), "r"(b1));
}
static __device__ __forceinline__ void cp_async16(unsigned dst, const void* src) {
    asm volatile("cp.async.ca.shared.global [%0], [%1], 16;" :: "r"(dst), "l"(src));
}
static __device__ __forceinline__ void cp_commit() {
    asm volatile("cp.async.commit_group;");
}
static __device__ __forceinline__ void cp_wait0() {
    asm volatile("cp.async.wait_group 0;");
}
static __device__ __forceinline__ __nv_bfloat162 f2bf2(float a, float b) {
    return __floats2bfloat162_rn(a, b);
}

// ---------------------------------------------------------------------------
// Prep: 210 blocks x 256 threads
// ---------------------------------------------------------------------------
__global__ void prep_kernel(const float* __restrict__ ln_w, const float* __restrict__ ln_b,
                            const float* __restrict__ Wd,   const float* __restrict__ bd,
                            const float* __restrict__ Wq,   const float* __restrict__ Wk,
                            const float* __restrict__ Wv,   const float* __restrict__ Wg,
                            const float* __restrict__ Wu,
                            const float* __restrict__ cn1_w, const float* __restrict__ cn1_b,
                            const float* __restrict__ cn2_w, const float* __restrict__ cn2_b,
                            const float* __restrict__ dn1_w, const float* __restrict__ dn2_w) {
    int bi = blockIdx.x, tid = threadIdx.x;
    if (bi < 32) {
        int idx = bi * 256 + tid;            // d*32 + r
        g_Wdh[idx] = __float2bfloat16_rn(ln_w[idx >> 5] * Wd[idx]);
    } else if (bi < 48) {
        int idx = (bi - 32) * 256 + tid;     // kk*128 + o
        int kk = idx >> 7, o = idx & 127, m = o >> 5, r = o & 31;
        const float* src = (m == 0) ? Wq : (m == 1) ? Wk : (m == 2) ? Wv : Wg;
        g_W4h[idx] = __float2bfloat16_rn(src[kk * Rv + r]);
    } else if (bi < 80) {
        int idx = (bi - 48) * 256 + tid;     // r*256 + d
        g_Wuh[idx] = __float2bfloat16_rn(Wu[idx]);
    } else if (bi < 144) {
        int j = bi - 80;
        g_dn1f8[j * Dv + tid] =
            __nv_cvt_float_to_fp8(dn1_w[tid * Hv + j] * FP8S, __NV_SATFINITE, __NV_E4M3);
    } else if (bi < 208) {
        int j = bi - 144;
        g_dn2f8[j * Dv + tid] =
            __nv_cvt_float_to_fp8(dn2_w[j * Dv + tid] * FP8S, __NV_SATFINITE, __NV_E4M3);
    } else if (bi == 208) {
        __shared__ float ssw[8][32], slb[8][32];
        int r = tid & 31, seg = tid >> 5;
        float sw = 0.f, lb = 0.f;
        for (int dd = 0; dd < 32; dd++) {
            int d = seg * 32 + dd;
            float wv = Wd[d * Rv + r];
            sw += ln_w[d] * wv;
            lb += ln_b[d] * wv;
        }
        ssw[seg][r] = sw; slb[seg][r] = lb;
        __syncthreads();
        if (tid < 32) {
            float a = 0.f, b2 = 0.f;
            #pragma unroll
            for (int s = 0; s < 8; s++) { a += ssw[s][tid]; b2 += slb[s][tid]; }
            g_SW[tid] = a;
            g_LB[tid] = b2 + bd[tid];
        }
    } else {
        __shared__ float hid[Hv];
        const float lc = logf(21.0f) / logf(1000.0f);
        if (tid < Hv) hid[tid] = geluf(lc * cn1_w[tid] + cn1_b[tid]);
        __syncthreads();
        float acc = cn2_b[tid];
        for (int j = 0; j < Hv; j++) acc += hid[j] * cn2_w[j * Dv + tid];
        g_logits[tid] = acc;
    }
}

// ---------------------------------------------------------------------------
// Fully-fused kernel: one CTA per (b,p). 256 thr, 8 warps, 4 CTAs/SM.
// ---------------------------------------------------------------------------
__global__ __launch_bounds__(256, 4) void fused_kernel(
    const float* __restrict__ x,
    const float* __restrict__ bg,
    const float* __restrict__ bu,
    const float* __restrict__ dn1_b,
    const float* __restrict__ dn2_b,
    const float* __restrict__ eps_p,
    float* __restrict__ out)
{
    __shared__ __align__(16) __nv_bfloat16 h_b[32 * HB];    // x tile, later wu_b
    __shared__ __align__(16) __nv_bfloat16 wd_b[Dv * WB];   // Wd tile, later mixed
    __shared__ __align__(16) __nv_bfloat16 w4_b[Rv * W4B];  // W4 tile
    __shared__ __align__(16) __nv_bfloat16 A_b[32 * AB];    // qn*sig(g)
    __shared__ __align__(16) __nv_bfloat16 hl_b[32 * AB];   // h_low (junk rows 0)
    __shared__ __align__(16) float cvsred[2 * Dv];          // sred partials
    __shared__ __align__(16) __half cv_h[Dv];               // cv in half
    __shared__ float mu_s[32], rs_s[32];
    __shared__ __align__(16) float sw_s[32], lb_s[32];
    __shared__ __align__(16) float bg_s[32];
    __shared__ __align__(16) float gfp_s[2 * Rv];
    __shared__ __align__(16) __half hid_h[Hv];              // data-MLP hidden (half)
    __shared__ __align__(16) float gate_s[Dv];

    __nv_bfloat16* mixed_b = wd_b;   // wd_b dead after ph4; reuse for mixed

    const int tid = threadIdx.x;
    const int lane = tid & 31;
    const int w = tid >> 5;
    const int bp = blockIdx.x;
    const int bb = bp / Pv, pp = bp % Pv;
    const int xrow = bb * Cv * PDv + pp * Dv;

    if (tid < 32) {
        sw_s[tid] = g_SW[tid];
        lb_s[tid] = g_LB[tid];
        bg_s[tid] = __ldg(&bg[tid]);
    }
    if (tid >= 21 && tid < 32) { mu_s[tid] = 0.f; rs_s[tid] = 0.f; }

    // ---- R1: x -> h_b (bf16) + cv; cp.async stage Wd + W4 ----------------
    {
        float s1 = 0.f, s2 = 0.f;
        #pragma unroll
        for (int c = 0; c < Cv; c++) {
            float v = x[xrow + c * PDv + tid];
            h_b[c * HB + tid] = __float2bfloat16_rn(v);
            s1 += v; s2 += v * v;
        }
        cv_h[tid] = __float2half_rn((s2 - s1 * s1 * (1.0f / 21.0f)) * (1.0f / 20.0f));
    }
    {
        unsigned wdbase = smem_u32(wd_b);
        #pragma unroll
        for (int i = 0; i < 4; i++) {
            int idx = tid + 256 * i;            // 1024 chunks of 16B
            int row = idx >> 2, ch = idx & 3;
            cp_async16(wdbase + (unsigned)((row * WB + ch * 8) * 2),
                       g_Wdh + row * Rv + ch * 8);
        }
        unsigned w4base = smem_u32(w4_b);
        #pragma unroll
        for (int i = 0; i < 2; i++) {
            int idx = tid + 256 * i;            // 512 chunks
            int row = idx >> 4, ch = idx & 15;
            cp_async16(w4base + (unsigned)((row * W4B + ch * 8) * 2),
                       g_W4h + row * 128 + ch * 8);
        }
        cp_commit();
    }
    __syncthreads();

    // ---- R2: LN stats + gate MLP1 (fp8, half2, thread-quad per j) --------
    #pragma unroll
    for (int ci = 0; ci < 3; ci++) {
        int c = w + 8 * ci;
        if (c < Cv) {
            float s = 0.f, ss = 0.f;
            #pragma unroll
            for (int k2 = 0; k2 < 4; k2++) {
                __nv_bfloat162 hv = *reinterpret_cast<const __nv_bfloat162*>(
                    &h_b[c * HB + 2 * lane + 64 * k2]);
                float2 f = __bfloat1622float2(hv);
                s += f.x + f.y; ss += f.x * f.x + f.y * f.y;
            }
            #pragma unroll
            for (int o = 16; o > 0; o >>= 1) {
                s  += __shfl_xor_sync(0xffffffffu, s, o);
                ss += __shfl_xor_sync(0xffffffffu, ss, o);
            }
            if (lane == 0) {
                float mu = s * (1.0f / 256.0f);
                float var = ss * (1.0f / 256.0f) - mu * mu;
                mu_s[c] = mu;
                rs_s[c] = rsqrtf(var + 1e-5f);
            }
        }
    }
    {
        // j = tid>>2 (64 outputs), quad q = tid&3 owns d in {8q+32k : k<8}
        const int j = tid >> 2, q = tid & 3;
        __half2 acc = __float2half2_rn(0.f);
        #pragma unroll
        for (int k = 0; k < 8; k++) {
            int d0 = 8 * q + 32 * k;
            uint4 cvr = *reinterpret_cast<const uint4*>(&cv_h[d0]);
            uint2 wv = __ldg(reinterpret_cast<const uint2*>(&g_dn1f8[j * Dv + d0]));
            acc = __hfma2(*reinterpret_cast<__half2*>(&cvr.x), fp8x2_h2(wv.x), acc);
            acc = __hfma2(*reinterpret_cast<__half2*>(&cvr.y), fp8x2_h2(wv.x >> 16), acc);
            acc = __hfma2(*reinterpret_cast<__half2*>(&cvr.z), fp8x2_h2(wv.y), acc);
            acc = __hfma2(*reinterpret_cast<__half2*>(&cvr.w), fp8x2_h2(wv.y >> 16), acc);
        }
        float2 pf = __half22float2(acc);
        float part = pf.x + pf.y;
        part += __shfl_xor_sync(0xffffffffu, part, 1);
        part += __shfl_xor_sync(0xffffffffu, part, 2);
        float hv = gelu_fast(part * FP8SI + __ldg(&dn1_b[j]));
        if (q == 0) hid_h[j] = __float2half_rn(hv);
    }
    cp_wait0();
    __syncthreads();

    // ---- R3: warps 0-3 ph4 MMA -> hl_b; warps 4-7 gate MLP2 (half2) ------
    if (w < 4) {
        const int mtile = w & 1;
        const int r0 = (w >> 1) * 16;
        const unsigned a_addr = smem_u32(h_b)
            + (unsigned)(((mtile * 16 + (lane & 15)) * HB + ((lane >> 4) << 3)) * 2);
        const unsigned b_addr0 = smem_u32(wd_b)
            + (unsigned)(((lane & 15) * WB + r0) * 2);
        const unsigned b_addr1 = b_addr0 + 16;
        float c0[4] = {0.f, 0.f, 0.f, 0.f};
        float c1[4] = {0.f, 0.f, 0.f, 0.f};
        #pragma unroll
        for (int k = 0; k < 16; k++) {
            unsigned a0, a1, a2, a3, b0, b1;
            ldsm_x4(a0, a1, a2, a3, a_addr + k * 32);
            ldsm_x2t(b0, b1, b_addr0 + k * 16 * WB * 2);
            mma16816(c0[0], c0[1], c0[2], c0[3], a0, a1, a2, a3, b0, b1);
            ldsm_x2t(b0, b1, b_addr1 + k * 16 * WB * 2);
            mma16816(c1[0], c1[1], c1[2], c1[3], a0, a1, a2, a3, b0, b1);
        }
        const int m0 = mtile * 16 + (lane >> 2);
        const int m1 = m0 + 8;
        const bool v0 = m0 < Cv, v1 = m1 < Cv;
        const float mu0 = mu_s[m0], rv0 = rs_s[m0];
        const float mu1 = mu_s[m1], rv1 = rs_s[m1];
        #pragma unroll
        for (int nt = 0; nt < 2; nt++) {
            const float* cc = nt ? c1 : c0;
            int col = r0 + nt * 8 + 2 * (lane & 3);
            float sw0 = sw_s[col], sw1 = sw_s[col + 1];
            float lb0 = lb_s[col], lb1 = lb_s[col + 1];
            float h00 = v0 ? (rv0 * (cc[0] - mu0 * sw0) + lb0) : 0.f;
            float h01 = v0 ? (rv0 * (cc[1] - mu0 * sw1) + lb1) : 0.f;
            float h10 = v1 ? (rv1 * (cc[2] - mu1 * sw0) + lb0) : 0.f;
            float h11 = v1 ? (rv1 * (cc[3] - mu1 * sw1) + lb1) : 0.f;
            *reinterpret_cast<__nv_bfloat162*>(&hl_b[m0 * AB + col]) = f2bf2(h00, h01);
            *reinterpret_cast<__nv_bfloat162*>(&hl_b[m1 * AB + col]) = f2bf2(h10, h11);
        }
    } else {
        const int local = tid - 128;
        const int dq = local & 63;            // d = 4dq .. 4dq+3
        const int jh = local >> 6;
        __half2 acc01 = __float2half2_rn(0.f), acc23 = acc01;
        #pragma unroll
        for (int j4 = 0; j4 < 8; j4++) {
            int j = 32 * jh + 4 * j4;
            uint2 hraw = *reinterpret_cast<const uint2*>(&hid_h[j]);
            __half2 hp01 = *reinterpret_cast<__half2*>(&hraw.x);
            __half2 hp23 = *reinterpret_cast<__half2*>(&hraw.y);
            #pragma unroll
            for (int t = 0; t < 4; t++) {
                unsigned wv = __ldg(reinterpret_cast<const unsigned*>(
                    &g_dn2f8[(j + t) * Dv + 4 * dq]));
                __half hj = (t == 0) ? __low2half(hp01) : (t == 1) ? __high2half(hp01)
                          : (t == 2) ? __low2half(hp23) : __high2half(hp23);
                __half2 hb = __half2half2(hj);
                acc01 = __hfma2(hb, fp8x2_h2(wv), acc01);
                acc23 = __hfma2(hb, fp8x2_h2(wv >> 16), acc23);
            }
        }
        float2 f01 = __half22float2(acc01);
        float2 f23 = __half22float2(acc23);
        *reinterpret_cast<float4*>(&cvsred[jh * Dv + 4 * dq]) =
            make_float4(f01.x, f01.y, f23.x, f23.y);
    }
    __syncthreads();

    // ---- R4: warps 0-3 ph5 MMA (QKVG); warps 4-7 gate finalize + Wu stage
    if (w < 4) {
        const int role = w & 1;      // 0: q&g, 1: k&v
        const int mt = w >> 1;
        const unsigned a_addr = smem_u32(hl_b)
            + (unsigned)(((mt * 16 + (lane & 15)) * AB + ((lane >> 4) << 3)) * 2);
        unsigned a0, a1, a2, a3, a4, a5, a6, a7;
        ldsm_x4(a0, a1, a2, a3, a_addr);
        ldsm_x4(a4, a5, a6, a7, a_addr + 32);
        const int ob1 = role ? 32 : 0;    // k : q
        const int ob2 = role ? 64 : 96;   // v : g
        const unsigned bbase = smem_u32(w4_b) + (unsigned)(((lane & 15) * W4B) * 2);
        const unsigned bk16 = 16 * W4B * 2;
        float c1v[16], c2v[16];
        #pragma unroll
        for (int i = 0; i < 16; i++) { c1v[i] = 0.f; c2v[i] = 0.f; }
        #pragma unroll
        for (int nb = 0; nb < 4; nb++) {
            unsigned b0, b1;
            ldsm_x2t(b0, b1, bbase + (ob1 + nb * 8) * 2);
            mma16816(c1v[4*nb], c1v[4*nb+1], c1v[4*nb+2], c1v[4*nb+3],
                     a0, a1, a2, a3, b0, b1);
            ldsm_x2t(b0, b1, bbase + bk16 + (ob1 + nb * 8) * 2);
            mma16816(c1v[4*nb], c1v[4*nb+1], c1v[4*nb+2], c1v[4*nb+3],
                     a4, a5, a6, a7, b0, b1);
            ldsm_x2t(b0, b1, bbase + (ob2 + nb * 8) * 2);
            mma16816(c2v[4*nb], c2v[4*nb+1], c2v[4*nb+2], c2v[4*nb+3],
                     a0, a1, a2, a3, b0, b1);
            ldsm_x2t(b0, b1, bbase + bk16 + (ob2 + nb * 8) * 2);
            mma16816(c2v[4*nb], c2v[4*nb+1], c2v[4*nb+2], c2v[4*nb+3],
                     a4, a5, a6, a7, b0, b1);
        }
        float qs0 = 0.f, qs1 = 0.f;
        #pragma unroll
        for (int nb = 0; nb < 4; nb++) {
            qs0 += c1v[4*nb] * c1v[4*nb] + c1v[4*nb+1] * c1v[4*nb+1];
            qs1 += c1v[4*nb+2] * c1v[4*nb+2] + c1v[4*nb+3] * c1v[4*nb+3];
        }
        qs0 += __shfl_xor_sync(0xffffffffu, qs0, 1);
        qs0 += __shfl_xor_sync(0xffffffffu, qs0, 2);
        qs1 += __shfl_xor_sync(0xffffffffu, qs1, 1);
        qs1 += __shfl_xor_sync(0xffffffffu, qs1, 2);
        float rn0 = rsqrtf(fmaxf(qs0, 1e-24f));
        float rn1 = rsqrtf(fmaxf(qs1, 1e-24f));
        if (role == 0) {
            const int m0 = mt * 16 + (lane >> 2);
            const int m1 = m0 + 8;
            #pragma unroll
            for (int nb = 0; nb < 4; nb++) {
                int rcol = nb * 8 + 2 * (lane & 3);
                float2 bgv = *reinterpret_cast<const float2*>(&bg_s[rcol]);
                float A0 = c1v[4*nb]   * rn0 * sigm(c2v[4*nb]   + bgv.x);
                float A1 = c1v[4*nb+1] * rn0 * sigm(c2v[4*nb+1] + bgv.y);
                float A2 = c1v[4*nb+2] * rn1 * sigm(c2v[4*nb+2] + bgv.x);
                float A3 = c1v[4*nb+3] * rn1 * sigm(c2v[4*nb+3] + bgv.y);
                *reinterpret_cast<__nv_bfloat162*>(&A_b[m0 * AB + rcol]) = f2bf2(A0, A1);
                *reinterpret_cast<__nv_bfloat162*>(&A_b[m1 * AB + rcol]) = f2bf2(A2, A3);
            }
        } else {
            #pragma unroll
            for (int nb = 0; nb < 4; nb++) {
                float g0 = c1v[4*nb]   * rn0 * c2v[4*nb]   + c1v[4*nb+2] * rn1 * c2v[4*nb+2];
                float g1 = c1v[4*nb+1] * rn0 * c2v[4*nb+1] + c1v[4*nb+3] * rn1 * c2v[4*nb+3];
                g0 += __shfl_xor_sync(0xffffffffu, g0, 4);
                g0 += __shfl_xor_sync(0xffffffffu, g0, 8);
                g0 += __shfl_xor_sync(0xffffffffu, g0, 16);
                g1 += __shfl_xor_sync(0xffffffffu, g1, 4);
                g1 += __shfl_xor_sync(0xffffffffu, g1, 8);
                g1 += __shfl_xor_sync(0xffffffffu, g1, 16);
                if (lane < 4) {
                    gfp_s[mt * 32 + nb * 8 + 2 * lane]     = g0;
                    gfp_s[mt * 32 + nb * 8 + 2 * lane + 1] = g1;
                }
            }
        }
    } else {
        // gate finalize: 2 d per thread
        const int local = tid - 128;
        const float ev = __ldg(eps_p);
        #pragma unroll
        for (int t = 0; t < 2; t++) {
            int dd = 2 * local + t;
            float dc = (cvsred[dd] + cvsred[Dv + dd]) * FP8SI;
            gate_s[dd] = sigm(__ldg(&g_logits[dd]) + ev * (dc + __ldg(&dn2_b[dd])));
        }
        // cp.async stage Wu into h_b (dead after ph4)
        unsigned wubase = smem_u32(h_b);
        #pragma unroll
        for (int i = 0; i < 8; i++) {
            int idx = local + 128 * i;           // 1024 chunks
            int row = idx >> 5, ch = idx & 31;
            cp_async16(wubase + (unsigned)((row * HB + ch * 8) * 2),
                       g_Wuh + row * Dv + ch * 8);
        }
        cp_commit();
        cp_wait0();
    }
    __syncthreads();   // gfp_s, gate_s, wu_b all ready

    // ---- R6: ph6 MMA ((A*gf) @ wu_b) -> mixed_b (gf computed inline) -----
    {
        const int mtile = w & 1;
        const int nb0 = (w >> 1) * 64;
        const unsigned a_addr = smem_u32(A_b)
            + (unsigned)(((mtile * 16 + (lane & 15)) * AB + ((lane >> 4) << 3)) * 2);
        unsigned a00, a01, a02, a03, a10, a11, a12, a13;
        ldsm_x4(a00, a01, a02, a03, a_addr);
        ldsm_x4(a10, a11, a12, a13, a_addr + 32);
        {
            int kc2 = 2 * (lane & 3);
            float2 p, q2;
            p = *reinterpret_cast<const float2*>(&gfp_s[kc2]);
            q2 = *reinterpret_cast<const float2*>(&gfp_s[32 + kc2]);
            __nv_bfloat162 s0 = f2bf2(p.x + q2.x, p.y + q2.y);
            p = *reinterpret_cast<const float2*>(&gfp_s[kc2 + 8]);
            q2 = *reinterpret_cast<const float2*>(&gfp_s[40 + kc2]);
            __nv_bfloat162 s1 = f2bf2(p.x + q2.x, p.y + q2.y);
            p = *reinterpret_cast<const float2*>(&gfp_s[kc2 + 16]);
            q2 = *reinterpret_cast<const float2*>(&gfp_s[48 + kc2]);
            __nv_bfloat162 s2 = f2bf2(p.x + q2.x, p.y + q2.y);
            p = *reinterpret_cast<const float2*>(&gfp_s[kc2 + 24]);
            q2 = *reinterpret_cast<const float2*>(&gfp_s[56 + kc2]);
            __nv_bfloat162 s3 = f2bf2(p.x + q2.x, p.y + q2.y);
            __nv_bfloat162* pa;
            pa = reinterpret_cast<__nv_bfloat162*>(&a00); *pa = __hmul2(*pa, s0);
            pa = reinterpret_cast<__nv_bfloat162*>(&a01); *pa = __hmul2(*pa, s0);
            pa = reinterpret_cast<__nv_bfloat162*>(&a02); *pa = __hmul2(*pa, s1);
            pa = reinterpret_cast<__nv_bfloat162*>(&a03); *pa = __hmul2(*pa, s1);
            pa = reinterpret_cast<__nv_bfloat162*>(&a10); *pa = __hmul2(*pa, s2);
            pa = reinterpret_cast<__nv_bfloat162*>(&a11); *pa = __hmul2(*pa, s2);
            pa = reinterpret_cast<__nv_bfloat162*>(&a12); *pa = __hmul2(*pa, s3);
            pa = reinterpret_cast<__nv_bfloat162*>(&a13); *pa = __hmul2(*pa, s3);
        }
        const unsigned b_base = smem_u32(h_b) + (unsigned)(((lane & 15) * HB) * 2);
        const int m0 = mtile * 16 + (lane >> 2);
        const int m1 = m0 + 8;
        #pragma unroll
        for (int t = 0; t < 8; t++) {
            int n0 = nb0 + t * 8;
            unsigned b0, b1, b2, b3;
            ldsm_x2t(b0, b1, b_base + n0 * 2);
            ldsm_x2t(b2, b3, b_base + 16 * HB * 2 + n0 * 2);
            float c0 = 0.f, c1 = 0.f, c2 = 0.f, c3 = 0.f;
            mma16816(c0, c1, c2, c3, a00, a01, a02, a03, b0, b1);
            mma16816(c0, c1, c2, c3, a10, a11, a12, a13, b2, b3);
            int d0 = n0 + 2 * (lane & 3);
            if (m0 < Cv)
                *reinterpret_cast<__nv_bfloat162*>(&mixed_b[m0 * MB + d0]) = f2bf2(c0, c1);
            if (m1 < Cv)
                *reinterpret_cast<__nv_bfloat162*>(&mixed_b[m1 * MB + d0]) = f2bf2(c2, c3);
        }
    }
    __syncthreads();

    // ---- R7: vectorized out = x + gate*(mixed + bu) ----------------------
    {
        const int col0 = 4 * (tid & 63);
        const int rg = tid >> 6;
        float4 gv4 = *reinterpret_cast<const float4*>(&gate_s[col0]);
        float4 bu4 = __ldg(reinterpret_cast<const float4*>(&bu[col0]));
        #pragma unroll
        for (int k = 0; k < 6; k++) {
            int c = rg + 4 * k;
            if (c < Cv) {
                uint2 mm = *reinterpret_cast<const uint2*>(&mixed_b[c * MB + col0]);
                float2 f01 = __bfloat1622float2(*reinterpret_cast<__nv_bfloat162*>(&mm.x));
                float2 f23 = __bfloat1622float2(*reinterpret_cast<__nv_bfloat162*>(&mm.y));
                int gi = xrow + c * PDv + col0;
                float4 xv = *reinterpret_cast<const float4*>(&x[gi]);
                float4 o;
                o.x = xv.x + gv4.x * (f01.x + bu4.x);
                o.y = xv.y + gv4.y * (f01.y + bu4.y);
                o.z = xv.z + gv4.z * (f23.x + bu4.z);
                o.w = xv.w + gv4.w * (f23.y + bu4.w);
                *reinterpret_cast<float4*>(&out[gi]) = o;
            }
        }
    }
}

// ---------------------------------------------------------------------------
extern "C" void kernel_launch(void* const* d_in, const int* in_sizes, int n_in,
                              void* d_out, int out_size) {
    const float* x     = (const float*)d_in[0];
    const float* ln_w  = (const float*)d_in[1];
    const float* ln_b  = (const float*)d_in[2];
    const float* Wd    = (const float*)d_in[3];
    const float* bd    = (const float*)d_in[4];
    const float* Wq    = (const float*)d_in[5];
    const float* Wk    = (const float*)d_in[6];
    const float* Wvp   = (const float*)d_in[7];
    const float* Wg    = (const float*)d_in[8];
    const float* bg    = (const float*)d_in[9];
    const float* Wu    = (const float*)d_in[10];
    const float* bu    = (const float*)d_in[11];
    const float* cn1_w = (const float*)d_in[12];
    const float* cn1_b = (const float*)d_in[13];
    const float* cn2_w = (const float*)d_in[14];
    const float* cn2_b = (const float*)d_in[15];
    const float* dn1_w = (const float*)d_in[16];
    const float* dn1_b = (const float*)d_in[17];
    const float* dn2_w = (const float*)d_in[18];
    const float* dn2_b = (const float*)d_in[19];
    const float* eps   = (const float*)d_in[20];
    float* out = (float*)d_out;

    prep_kernel<<<210, 256>>>(ln_w, ln_b, Wd, bd, Wq, Wk, Wvp, Wg, Wu,
                              cn1_w, cn1_b, cn2_w, cn2_b, dn1_w, dn2_w);
    fused_kernel<<<BPv, 256>>>(x, bg, bu, dn1_b, dn2_b, eps, out);
}

// round 15
// speedup vs baseline: 1.3019x; 1.3019x over previous
#include <cuda_runtime.h>
#include <cuda_bf16.h>
#include <cuda_fp16.h>
#include <cuda_fp8.h>
#include <math.h>

#define Bv 64
#define Cv 21
#define Pv 96
#define Dv 256
#define Rv 32
#define Hv 64
#define BPv (Bv*Pv)
#define PDv (Pv*Dv)

// padded smem strides (elements); all 16B multiples with odd-16B rotation
#define HB  264   // h_b / wu_b row stride (528B)
#define WB  40    // wd_b row stride (80B)
#define AB  40    // A_b / hl_b row stride (80B)
#define W4B 136   // w4_b row stride (272B)
#define MB  264   // mixed row stride

#define FP8S 32.0f
#define FP8SI (1.0f/32.0f)

// ---------------- device-global precomputed weights -------------------------
__device__ __align__(16) __nv_bfloat16 g_Wdh[Dv*Rv];        // [d][r] = bf16(ln_w*Wd)
__device__ __align__(16) __nv_bfloat16 g_W4h[Rv*128];       // [kk][o]
__device__ __align__(16) __nv_bfloat16 g_Wuh[Rv*Dv];        // [r][d]
__device__ __align__(16) __nv_fp8_storage_t g_dn1f8[Hv*Dv]; // [j][d]
__device__ __align__(16) __nv_fp8_storage_t g_dn2f8[Hv*Dv]; // [j][d]
__device__ float g_SW[Rv];
__device__ float g_LB[Rv];
__device__ float g_logits[Dv];

static __device__ __forceinline__ float geluf(float x) {
    return 0.5f * x * (1.0f + erff(x * 0.70710678118654752f));
}
static __device__ __forceinline__ float gelu_fast(float x) {
    float z = 0.7978845608f * fmaf(0.044715f, x * x * x, x);
    float e = __expf(2.f * z);
    float th = 1.f - __fdividef(2.f, e + 1.f);
    return 0.5f * x * (1.f + th);
}
static __device__ __forceinline__ float sigm(float x) {
    return 1.0f / (1.0f + __expf(-x));
}
static __device__ __forceinline__ __half2 fp8x2_h2(unsigned v) {
    __half2_raw hr = __nv_cvt_fp8x2_to_halfraw2((__nv_fp8x2_storage_t)(v & 0xffffu),
                                                __NV_E4M3);
    return *reinterpret_cast<__half2*>(&hr);
}
static __device__ __forceinline__ unsigned smem_u32(const void* p) {
    return (unsigned)__cvta_generic_to_shared(p);
}
static __device__ __forceinline__ void ldsm_x4(unsigned& r0, unsigned& r1,
                                               unsigned& r2, unsigned& r3, unsigned a) {
    asm volatile("ldmatrix.sync.aligned.m8n8.x4.shared.b16 {%0,%1,%2,%3}, [%4];"
                 : "=r"(r0), "=r"(r1), "=r"(r2), "=r"(r3) : "r"(a));
}
static __device__ __forceinline__ void ldsm_x2t(unsigned& r0, unsigned& r1, unsigned a) {
    asm volatile("ldmatrix.sync.aligned.m8n8.x2.trans.shared.b16 {%0,%1}, [%2];"
                 : "=r"(r0), "=r"(r1) : "r"(a));
}
static __device__ __forceinline__ void mma16816(float& c0, float& c1, float& c2, float& c3,
                                                unsigned a0, unsigned a1, unsigned a2, unsigned a3,
                                                unsigned b0, unsigned b1) {
    asm volatile("mma.sync.aligned.m16n8k16.row.col.f32.bf16.bf16.f32 "
                 "{%0,%1,%2,%3}, {%4,%5,%6,%7}, {%8,%9}, {%0,%1,%2,%3};"
                 : "+f"(c0), "+f"(c1), "+f"(c2), "+f"(c3)
                 : "r"(a0), "r"(a1), "r"(a2), "r"(a3), "r"(b0), "r"(b1));
}
static __device__ __forceinline__ void cp_async16(unsigned dst, const void* src) {
    asm volatile("cp.async.ca.shared.global [%0], [%1], 16;" :: "r"(dst), "l"(src));
}
static __device__ __forceinline__ void cp_commit() {
    asm volatile("cp.async.commit_group;");
}
static __device__ __forceinline__ void cp_wait0() {
    asm volatile("cp.async.wait_group 0;");
}
static __device__ __forceinline__ __nv_bfloat162 f2bf2(float a, float b) {
    return __floats2bfloat162_rn(a, b);
}

// ---------------------------------------------------------------------------
// Prep: 210 blocks x 256 threads
// ---------------------------------------------------------------------------
__global__ void prep_kernel(const float* __restrict__ ln_w, const float* __restrict__ ln_b,
                            const float* __restrict__ Wd,   const float* __restrict__ bd,
                            const float* __restrict__ Wq,   const float* __restrict__ Wk,
                            const float* __restrict__ Wv,   const float* __restrict__ Wg,
                            const float* __restrict__ Wu,
                            const float* __restrict__ cn1_w, const float* __restrict__ cn1_b,
                            const float* __restrict__ cn2_w, const float* __restrict__ cn2_b,
                            const float* __restrict__ dn1_w, const float* __restrict__ dn2_w) {
    int bi = blockIdx.x, tid = threadIdx.x;
    if (bi < 32) {
        int idx = bi * 256 + tid;            // d*32 + r
        g_Wdh[idx] = __float2bfloat16_rn(ln_w[idx >> 5] * Wd[idx]);
    } else if (bi < 48) {
        int idx = (bi - 32) * 256 + tid;     // kk*128 + o
        int kk = idx >> 7, o = idx & 127, m = o >> 5, r = o & 31;
        const float* src = (m == 0) ? Wq : (m == 1) ? Wk : (m == 2) ? Wv : Wg;
        g_W4h[idx] = __float2bfloat16_rn(src[kk * Rv + r]);
    } else if (bi < 80) {
        int idx = (bi - 48) * 256 + tid;     // r*256 + d
        g_Wuh[idx] = __float2bfloat16_rn(Wu[idx]);
    } else if (bi < 144) {
        int j = bi - 80;
        g_dn1f8[j * Dv + tid] =
            __nv_cvt_float_to_fp8(dn1_w[tid * Hv + j] * FP8S, __NV_SATFINITE, __NV_E4M3);
    } else if (bi < 208) {
        int j = bi - 144;
        g_dn2f8[j * Dv + tid] =
            __nv_cvt_float_to_fp8(dn2_w[j * Dv + tid] * FP8S, __NV_SATFINITE, __NV_E4M3);
    } else if (bi == 208) {
        __shared__ float ssw[8][32], slb[8][32];
        int r = tid & 31, seg = tid >> 5;
        float sw = 0.f, lb = 0.f;
        for (int dd = 0; dd < 32; dd++) {
            int d = seg * 32 + dd;
            float wv = Wd[d * Rv + r];
            sw += ln_w[d] * wv;
            lb += ln_b[d] * wv;
        }
        ssw[seg][r] = sw; slb[seg][r] = lb;
        __syncthreads();
        if (tid < 32) {
            float a = 0.f, b2 = 0.f;
            #pragma unroll
            for (int s = 0; s < 8; s++) { a += ssw[s][tid]; b2 += slb[s][tid]; }
            g_SW[tid] = a;
            g_LB[tid] = b2 + bd[tid];
        }
    } else {
        __shared__ float hid[Hv];
        const float lc = logf(21.0f) / logf(1000.0f);
        if (tid < Hv) hid[tid] = geluf(lc * cn1_w[tid] + cn1_b[tid]);
        __syncthreads();
        float acc = cn2_b[tid];
        for (int j = 0; j < Hv; j++) acc += hid[j] * cn2_w[j * Dv + tid];
        g_logits[tid] = acc;
    }
}

// ---------------------------------------------------------------------------
// Fully-fused kernel: one CTA per (b,p). 256 thr, 8 warps, 4 CTAs/SM.
// ---------------------------------------------------------------------------
__global__ __launch_bounds__(256, 4) void fused_kernel(
    const float* __restrict__ x,
    const float* __restrict__ bg,
    const float* __restrict__ bu,
    const float* __restrict__ dn1_b,
    const float* __restrict__ dn2_b,
    const float* __restrict__ eps_p,
    float* __restrict__ out)
{
    __shared__ __align__(16) __nv_bfloat16 h_b[32 * HB];    // x tile, later wu_b
    __shared__ __align__(16) __nv_bfloat16 wd_b[Dv * WB];   // Wd tile, later mixed
    __shared__ __align__(16) __nv_bfloat16 w4_b[Rv * W4B];  // W4 tile
    __shared__ __align__(16) __nv_bfloat16 A_b[32 * AB];    // qn*sig(g)
    __shared__ __align__(16) __nv_bfloat16 hl_b[32 * AB];   // h_low (junk rows 0)
    __shared__ __align__(16) float cvsred[2 * Dv];          // sred partials
    __shared__ __align__(16) __half cv_h[Dv];               // cv in half
    __shared__ float mu_s[32], rs_s[32];
    __shared__ __align__(16) float sw_s[32], lb_s[32];
    __shared__ __align__(16) float bg_s[32];
    __shared__ __align__(16) float gfp_s[2 * Rv];
    __shared__ __align__(16) __half hid_h[Hv];              // data-MLP hidden (half)
    __shared__ __align__(16) float gate_s[Dv];

    __nv_bfloat16* mixed_b = wd_b;   // wd_b dead after ph4; reuse for mixed

    const int tid = threadIdx.x;
    const int lane = tid & 31;
    const int w = tid >> 5;
    const int bp = blockIdx.x;
    const int bb = bp / Pv, pp = bp % Pv;
    const int xrow = bb * Cv * PDv + pp * Dv;

    if (tid < 32) {
        sw_s[tid] = g_SW[tid];
        lb_s[tid] = g_LB[tid];
        bg_s[tid] = __ldg(&bg[tid]);
    }
    if (tid >= 21 && tid < 32) { mu_s[tid] = 0.f; rs_s[tid] = 0.f; }

    // ---- R1: x -> h_b (bf16) + cv; cp.async stage Wd + W4 ----------------
    {
        float s1 = 0.f, s2 = 0.f;
        #pragma unroll
        for (int c = 0; c < Cv; c++) {
            float v = x[xrow + c * PDv + tid];
            h_b[c * HB + tid] = __float2bfloat16_rn(v);
            s1 += v; s2 += v * v;
        }
        cv_h[tid] = __float2half_rn((s2 - s1 * s1 * (1.0f / 21.0f)) * (1.0f / 20.0f));
    }
    {
        unsigned wdbase = smem_u32(wd_b);
        #pragma unroll
        for (int i = 0; i < 4; i++) {
            int idx = tid + 256 * i;            // 1024 chunks of 16B
            int row = idx >> 2, ch = idx & 3;
            cp_async16(wdbase + (unsigned)((row * WB + ch * 8) * 2),
                       g_Wdh + row * Rv + ch * 8);
        }
        unsigned w4base = smem_u32(w4_b);
        #pragma unroll
        for (int i = 0; i < 2; i++) {
            int idx = tid + 256 * i;            // 512 chunks
            int row = idx >> 4, ch = idx & 15;
            cp_async16(w4base + (unsigned)((row * W4B + ch * 8) * 2),
                       g_W4h + row * 128 + ch * 8);
        }
        cp_commit();
    }
    __syncthreads();

    // ---- R2: LN stats + gate MLP1 (fp8, half2) ---------------------------
    #pragma unroll
    for (int ci = 0; ci < 3; ci++) {
        int c = w + 8 * ci;
        if (c < Cv) {
            float s = 0.f, ss = 0.f;
            #pragma unroll
            for (int k2 = 0; k2 < 4; k2++) {
                __nv_bfloat162 hv = *reinterpret_cast<const __nv_bfloat162*>(
                    &h_b[c * HB + 2 * lane + 64 * k2]);
                float2 f = __bfloat1622float2(hv);
                s += f.x + f.y; ss += f.x * f.x + f.y * f.y;
            }
            #pragma unroll
            for (int o = 16; o > 0; o >>= 1) {
                s  += __shfl_xor_sync(0xffffffffu, s, o);
                ss += __shfl_xor_sync(0xffffffffu, ss, o);
            }
            if (lane == 0) {
                float mu = s * (1.0f / 256.0f);
                float var = ss * (1.0f / 256.0f) - mu * mu;
                mu_s[c] = mu;
                rs_s[c] = rsqrtf(var + 1e-5f);
            }
        }
    }
    {
        // lane owns d-range [8*lane, 8*lane+8) as 4 half2
        uint4 cvr = *reinterpret_cast<const uint4*>(&cv_h[8 * lane]);
        __half2 c0 = *reinterpret_cast<__half2*>(&cvr.x);
        __half2 c1 = *reinterpret_cast<__half2*>(&cvr.y);
        __half2 c2 = *reinterpret_cast<__half2*>(&cvr.z);
        __half2 c3 = *reinterpret_cast<__half2*>(&cvr.w);
        #pragma unroll
        for (int jj = 0; jj < 8; jj++) {
            int j = w * 8 + jj;
            uint2 wv = __ldg(reinterpret_cast<const uint2*>(&g_dn1f8[j * Dv + 8 * lane]));
            __half2 p = __hmul2(c3, fp8x2_h2(wv.y >> 16));
            p = __hfma2(c2, fp8x2_h2(wv.y), p);
            p = __hfma2(c1, fp8x2_h2(wv.x >> 16), p);
            p = __hfma2(c0, fp8x2_h2(wv.x), p);
            float2 pf = __half22float2(p);
            float part = pf.x + pf.y;
            #pragma unroll
            for (int o = 16; o > 0; o >>= 1)
                part += __shfl_xor_sync(0xffffffffu, part, o);
            if (lane == 0)
                hid_h[j] = __float2half_rn(gelu_fast(part * FP8SI + __ldg(&dn1_b[j])));
        }
    }
    cp_wait0();
    __syncthreads();

    // ---- R3: warps 0-3 ph4 MMA -> hl_b; warps 4-7 gate MLP2 (half2) ------
    if (w < 4) {
        const int mtile = w & 1;
        const int r0 = (w >> 1) * 16;
        const unsigned a_addr = smem_u32(h_b)
            + (unsigned)(((mtile * 16 + (lane & 15)) * HB + ((lane >> 4) << 3)) * 2);
        const unsigned b_addr0 = smem_u32(wd_b)
            + (unsigned)(((lane & 15) * WB + r0) * 2);
        const unsigned b_addr1 = b_addr0 + 16;
        float c0[4] = {0.f, 0.f, 0.f, 0.f};
        float c1[4] = {0.f, 0.f, 0.f, 0.f};
        #pragma unroll
        for (int k = 0; k < 16; k++) {
            unsigned a0, a1, a2, a3, b0, b1;
            ldsm_x4(a0, a1, a2, a3, a_addr + k * 32);
            ldsm_x2t(b0, b1, b_addr0 + k * 16 * WB * 2);
            mma16816(c0[0], c0[1], c0[2], c0[3], a0, a1, a2, a3, b0, b1);
            ldsm_x2t(b0, b1, b_addr1 + k * 16 * WB * 2);
            mma16816(c1[0], c1[1], c1[2], c1[3], a0, a1, a2, a3, b0, b1);
        }
        const int m0 = mtile * 16 + (lane >> 2);
        const int m1 = m0 + 8;
        const bool v0 = m0 < Cv, v1 = m1 < Cv;
        const float mu0 = mu_s[m0], rv0 = rs_s[m0];
        const float mu1 = mu_s[m1], rv1 = rs_s[m1];
        #pragma unroll
        for (int nt = 0; nt < 2; nt++) {
            const float* cc = nt ? c1 : c0;
            int col = r0 + nt * 8 + 2 * (lane & 3);
            float sw0 = sw_s[col], sw1 = sw_s[col + 1];
            float lb0 = lb_s[col], lb1 = lb_s[col + 1];
            float h00 = v0 ? (rv0 * (cc[0] - mu0 * sw0) + lb0) : 0.f;
            float h01 = v0 ? (rv0 * (cc[1] - mu0 * sw1) + lb1) : 0.f;
            float h10 = v1 ? (rv1 * (cc[2] - mu1 * sw0) + lb0) : 0.f;
            float h11 = v1 ? (rv1 * (cc[3] - mu1 * sw1) + lb1) : 0.f;
            *reinterpret_cast<__nv_bfloat162*>(&hl_b[m0 * AB + col]) = f2bf2(h00, h01);
            *reinterpret_cast<__nv_bfloat162*>(&hl_b[m1 * AB + col]) = f2bf2(h10, h11);
        }
    } else {
        const int local = tid - 128;
        const int dq = local & 63;            // d = 4dq .. 4dq+3
        const int jh = local >> 6;
        __half2 acc01 = __float2half2_rn(0.f), acc23 = acc01;
        #pragma unroll
        for (int j4 = 0; j4 < 8; j4++) {
            int j = 32 * jh + 4 * j4;
            uint2 hraw = *reinterpret_cast<const uint2*>(&hid_h[j]);
            __half2 hp01 = *reinterpret_cast<__half2*>(&hraw.x);
            __half2 hp23 = *reinterpret_cast<__half2*>(&hraw.y);
            #pragma unroll
            for (int t = 0; t < 4; t++) {
                unsigned wv = __ldg(reinterpret_cast<const unsigned*>(
                    &g_dn2f8[(j + t) * Dv + 4 * dq]));
                __half hj = (t == 0) ? __low2half(hp01) : (t == 1) ? __high2half(hp01)
                          : (t == 2) ? __low2half(hp23) : __high2half(hp23);
                __half2 hb = __half2half2(hj);
                acc01 = __hfma2(hb, fp8x2_h2(wv), acc01);
                acc23 = __hfma2(hb, fp8x2_h2(wv >> 16), acc23);
            }
        }
        float2 f01 = __half22float2(acc01);
        float2 f23 = __half22float2(acc23);
        *reinterpret_cast<float4*>(&cvsred[jh * Dv + 4 * dq]) =
            make_float4(f01.x, f01.y, f23.x, f23.y);
    }
    __syncthreads();

    // ---- R4: warps 0-3 ph5 MMA (QKVG); warps 4-7 gate finalize + Wu stage
    if (w < 4) {
        const int role = w & 1;      // 0: q&g, 1: k&v
        const int mt = w >> 1;
        const unsigned a_addr = smem_u32(hl_b)
            + (unsigned)(((mt * 16 + (lane & 15)) * AB + ((lane >> 4) << 3)) * 2);
        unsigned a0, a1, a2, a3, a4, a5, a6, a7;
        ldsm_x4(a0, a1, a2, a3, a_addr);
        ldsm_x4(a4, a5, a6, a7, a_addr + 32);
        const int ob1 = role ? 32 : 0;    // k : q
        const int ob2 = role ? 64 : 96;   // v : g
        const unsigned bbase = smem_u32(w4_b) + (unsigned)(((lane & 15) * W4B) * 2);
        const unsigned bk16 = 16 * W4B * 2;
        float c1v[16], c2v[16];
        #pragma unroll
        for (int i = 0; i < 16; i++) { c1v[i] = 0.f; c2v[i] = 0.f; }
        #pragma unroll
        for (int nb = 0; nb < 4; nb++) {
            unsigned b0, b1;
            ldsm_x2t(b0, b1, bbase + (ob1 + nb * 8) * 2);
            mma16816(c1v[4*nb], c1v[4*nb+1], c1v[4*nb+2], c1v[4*nb+3],
                     a0, a1, a2, a3, b0, b1);
            ldsm_x2t(b0, b1, bbase + bk16 + (ob1 + nb * 8) * 2);
            mma16816(c1v[4*nb], c1v[4*nb+1], c1v[4*nb+2], c1v[4*nb+3],
                     a4, a5, a6, a7, b0, b1);
            ldsm_x2t(b0, b1, bbase + (ob2 + nb * 8) * 2);
            mma16816(c2v[4*nb], c2v[4*nb+1], c2v[4*nb+2], c2v[4*nb+3],
                     a0, a1, a2, a3, b0, b1);
            ldsm_x2t(b0, b1, bbase + bk16 + (ob2 + nb * 8) * 2);
            mma16816(c2v[4*nb], c2v[4*nb+1], c2v[4*nb+2], c2v[4*nb+3],
                     a4, a5, a6, a7, b0, b1);
        }
        float qs0 = 0.f, qs1 = 0.f;
        #pragma unroll
        for (int nb = 0; nb < 4; nb++) {
            qs0 += c1v[4*nb] * c1v[4*nb] + c1v[4*nb+1] * c1v[4*nb+1];
            qs1 += c1v[4*nb+2] * c1v[4*nb+2] + c1v[4*nb+3] * c1v[4*nb+3];
        }
        qs0 += __shfl_xor_sync(0xffffffffu, qs0, 1);
        qs0 += __shfl_xor_sync(0xffffffffu, qs0, 2);
        qs1 += __shfl_xor_sync(0xffffffffu, qs1, 1);
        qs1 += __shfl_xor_sync(0xffffffffu, qs1, 2);
        float rn0 = rsqrtf(fmaxf(qs0, 1e-24f));
        float rn1 = rsqrtf(fmaxf(qs1, 1e-24f));
        if (role == 0) {
            const int m0 = mt * 16 + (lane >> 2);
            const int m1 = m0 + 8;
            #pragma unroll
            for (int nb = 0; nb < 4; nb++) {
                int rcol = nb * 8 + 2 * (lane & 3);
                float2 bgv = *reinterpret_cast<const float2*>(&bg_s[rcol]);
                float A0 = c1v[4*nb]   * rn0 * sigm(c2v[4*nb]   + bgv.x);
                float A1 = c1v[4*nb+1] * rn0 * sigm(c2v[4*nb+1] + bgv.y);
                float A2 = c1v[4*nb+2] * rn1 * sigm(c2v[4*nb+2] + bgv.x);
                float A3 = c1v[4*nb+3] * rn1 * sigm(c2v[4*nb+3] + bgv.y);
                *reinterpret_cast<__nv_bfloat162*>(&A_b[m0 * AB + rcol]) = f2bf2(A0, A1);
                *reinterpret_cast<__nv_bfloat162*>(&A_b[m1 * AB + rcol]) = f2bf2(A2, A3);
            }
        } else {
            #pragma unroll
            for (int nb = 0; nb < 4; nb++) {
                float g0 = c1v[4*nb]   * rn0 * c2v[4*nb]   + c1v[4*nb+2] * rn1 * c2v[4*nb+2];
                float g1 = c1v[4*nb+1] * rn0 * c2v[4*nb+1] + c1v[4*nb+3] * rn1 * c2v[4*nb+3];
                g0 += __shfl_xor_sync(0xffffffffu, g0, 4);
                g0 += __shfl_xor_sync(0xffffffffu, g0, 8);
                g0 += __shfl_xor_sync(0xffffffffu, g0, 16);
                g1 += __shfl_xor_sync(0xffffffffu, g1, 4);
                g1 += __shfl_xor_sync(0xffffffffu, g1, 8);
                g1 += __shfl_xor_sync(0xffffffffu, g1, 16);
                if (lane < 4) {
                    gfp_s[mt * 32 + nb * 8 + 2 * lane]     = g0;
                    gfp_s[mt * 32 + nb * 8 + 2 * lane + 1] = g1;
                }
            }
        }
    } else {
        // gate finalize: 2 d per thread
        const int local = tid - 128;
        const float ev = __ldg(eps_p);
        #pragma unroll
        for (int t = 0; t < 2; t++) {
            int dd = 2 * local + t;
            float dc = (cvsred[dd] + cvsred[Dv + dd]) * FP8SI;
            gate_s[dd] = sigm(__ldg(&g_logits[dd]) + ev * (dc + __ldg(&dn2_b[dd])));
        }
        // cp.async stage Wu into h_b (dead after ph4)
        unsigned wubase = smem_u32(h_b);
        #pragma unroll
        for (int i = 0; i < 8; i++) {
            int idx = local + 128 * i;           // 1024 chunks
            int row = idx >> 5, ch = idx & 31;
            cp_async16(wubase + (unsigned)((row * HB + ch * 8) * 2),
                       g_Wuh + row * Dv + ch * 8);
        }
        cp_commit();
        cp_wait0();
    }
    __syncthreads();   // gfp_s, gate_s, A_b, wu_b all ready

    // ---- R6: ph6 MMA ((A*gf) @ wu_b) -> mixed_b (gf computed inline) -----
    {
        const int mtile = w & 1;
        const int nb0 = (w >> 1) * 64;
        const unsigned a_addr = smem_u32(A_b)
            + (unsigned)(((mtile * 16 + (lane & 15)) * AB + ((lane >> 4) << 3)) * 2);
        unsigned a00, a01, a02, a03, a10, a11, a12, a13;
        ldsm_x4(a00, a01, a02, a03, a_addr);
        ldsm_x4(a10, a11, a12, a13, a_addr + 32);
        {
            int kc2 = 2 * (lane & 3);
            float2 p, q2;
            p = *reinterpret_cast<const float2*>(&gfp_s[kc2]);
            q2 = *reinterpret_cast<const float2*>(&gfp_s[32 + kc2]);
            __nv_bfloat162 s0 = f2bf2(p.x + q2.x, p.y + q2.y);
            p = *reinterpret_cast<const float2*>(&gfp_s[kc2 + 8]);
            q2 = *reinterpret_cast<const float2*>(&gfp_s[40 + kc2]);
            __nv_bfloat162 s1 = f2bf2(p.x + q2.x, p.y + q2.y);
            p = *reinterpret_cast<const float2*>(&gfp_s[kc2 + 16]);
            q2 = *reinterpret_cast<const float2*>(&gfp_s[48 + kc2]);
            __nv_bfloat162 s2 = f2bf2(p.x + q2.x, p.y + q2.y);
            p = *reinterpret_cast<const float2*>(&gfp_s[kc2 + 24]);
            q2 = *reinterpret_cast<const float2*>(&gfp_s[56 + kc2]);
            __nv_bfloat162 s3 = f2bf2(p.x + q2.x, p.y + q2.y);
            __nv_bfloat162* pa;
            pa = reinterpret_cast<__nv_bfloat162*>(&a00); *pa = __hmul2(*pa, s0);
            pa = reinterpret_cast<__nv_bfloat162*>(&a01); *pa = __hmul2(*pa, s0);
            pa = reinterpret_cast<__nv_bfloat162*>(&a02); *pa = __hmul2(*pa, s1);
            pa = reinterpret_cast<__nv_bfloat162*>(&a03); *pa = __hmul2(*pa, s1);
            pa = reinterpret_cast<__nv_bfloat162*>(&a10); *pa = __hmul2(*pa, s2);
            pa = reinterpret_cast<__nv_bfloat162*>(&a11); *pa = __hmul2(*pa, s2);
            pa = reinterpret_cast<__nv_bfloat162*>(&a12); *pa = __hmul2(*pa, s3);
            pa = reinterpret_cast<__nv_bfloat162*>(&a13); *pa = __hmul2(*pa, s3);
        }
        const unsigned b_base = smem_u32(h_b) + (unsigned)(((lane & 15) * HB) * 2);
        const int m0 = mtile * 16 + (lane >> 2);
        const int m1 = m0 + 8;
        #pragma unroll
        for (int t = 0; t < 8; t++) {
            int n0 = nb0 + t * 8;
            unsigned b0, b1, b2, b3;
            ldsm_x2t(b0, b1, b_base + n0 * 2);
            ldsm_x2t(b2, b3, b_base + 16 * HB * 2 + n0 * 2);
            float c0 = 0.f, c1 = 0.f, c2 = 0.f, c3 = 0.f;
            mma16816(c0, c1, c2, c3, a00, a01, a02, a03, b0, b1);
            mma16816(c0, c1, c2, c3, a10, a11, a12, a13, b2, b3);
            int d0 = n0 + 2 * (lane & 3);
            if (m0 < Cv)
                *reinterpret_cast<__nv_bfloat162*>(&mixed_b[m0 * MB + d0]) = f2bf2(c0, c1);
            if (m1 < Cv)
                *reinterpret_cast<__nv_bfloat162*>(&mixed_b[m1 * MB + d0]) = f2bf2(c2, c3);
        }
    }
    __syncthreads();

    // ---- R7: vectorized out = x + gate*(mixed + bu) ----------------------
    {
        const int col0 = 4 * (tid & 63);
        const int rg = tid >> 6;
        float4 gv4 = *reinterpret_cast<const float4*>(&gate_s[col0]);
        float4 bu4 = __ldg(reinterpret_cast<const float4*>(&bu[col0]));
        #pragma unroll
        for (int k = 0; k < 6; k++) {
            int c = rg + 4 * k;
            if (c < Cv) {
                uint2 mm = *reinterpret_cast<const uint2*>(&mixed_b[c * MB + col0]);
                float2 f01 = __bfloat1622float2(*reinterpret_cast<__nv_bfloat162*>(&mm.x));
                float2 f23 = __bfloat1622float2(*reinterpret_cast<__nv_bfloat162*>(&mm.y));
                int gi = xrow + c * PDv + col0;
                float4 xv = *reinterpret_cast<const float4*>(&x[gi]);
                float4 o;
                o.x = xv.x + gv4.x * (f01.x + bu4.x);
                o.y = xv.y + gv4.y * (f01.y + bu4.y);
                o.z = xv.z + gv4.z * (f23.x + bu4.z);
                o.w = xv.w + gv4.w * (f23.y + bu4.w);
                *reinterpret_cast<float4*>(&out[gi]) = o;
            }
        }
    }
}

// ---------------------------------------------------------------------------
extern "C" void kernel_launch(void* const* d_in, const int* in_sizes, int n_in,
                              void* d_out, int out_size) {
    const float* x     = (const float*)d_in[0];
    const float* ln_w  = (const float*)d_in[1];
    const float* ln_b  = (const float*)d_in[2];
    const float* Wd    = (const float*)d_in[3];
    const float* bd    = (const float*)d_in[4];
    const float* Wq    = (const float*)d_in[5];
    const float* Wk    = (const float*)d_in[6];
    const float* Wvp   = (const float*)d_in[7];
    const float* Wg    = (const float*)d_in[8];
    const float* bg    = (const float*)d_in[9];
    const float* Wu    = (const float*)d_in[10];
    const float* bu    = (const float*)d_in[11];
    const float* cn1_w = (const float*)d_in[12];
    const float* cn1_b = (const float*)d_in[13];
    const float* cn2_w = (const float*)d_in[14];
    const float* cn2_b = (const float*)d_in[15];
    const float* dn1_w = (const float*)d_in[16];
    const float* dn1_b = (const float*)d_in[17];
    const float* dn2_w = (const float*)d_in[18];
    const float* dn2_b = (const float*)d_in[19];
    const float* eps   = (const float*)d_in[20];
    float* out = (float*)d_out;

    prep_kernel<<<210, 256>>>(ln_w, ln_b, Wd, bd, Wq, Wk, Wvp, Wg, Wu,
                              cn1_w, cn1_b, cn2_w, cn2_b, dn1_w, dn2_w);
    fused_kernel<<<BPv, 256>>>(x, bg, bu, dn1_b, dn2_b, eps, out);
}

// round 16
// speedup vs baseline: 1.5616x; 1.1995x over previous
#include <cuda_runtime.h>
#include <cuda_bf16.h>
#include <cuda_fp16.h>
#include <cuda_fp8.h>
#include <math.h>

#define Bv 64
#define Cv 21
#define Pv 96
#define Dv 256
#define Rv 32
#define Hv 64
#define BPv (Bv*Pv)
#define PDv (Pv*Dv)

// padded smem strides (elements); all 16B multiples with odd-16B rotation
#define HB  264   // h_b / wu_b row stride (528B)
#define WB  40    // wd_b row stride (80B)
#define AB  40    // A_b / hl_b row stride (80B)
#define W4B 136   // w4_b row stride (272B)
#define MB  264   // mixed row stride

#define FP8S 32.0f
#define FP8SI (1.0f/32.0f)

// ---------------- device-global precomputed weights -------------------------
__device__ __align__(16) __nv_bfloat16 g_Wdh[Dv*Rv];        // [d][r] = bf16(ln_w*Wd)
__device__ __align__(16) __nv_bfloat16 g_W4h[Rv*128];       // [kk][o]
__device__ __align__(16) __nv_bfloat16 g_Wuh[Rv*Dv];        // [r][d]
__device__ __align__(16) __nv_fp8_storage_t g_dn1f8[Hv*Dv]; // [j][d]
__device__ __align__(16) __nv_fp8_storage_t g_dn2f8[Hv*Dv]; // [j][d]
__device__ float g_SW[Rv];
__device__ float g_LB[Rv];
__device__ float g_logits[Dv];

static __device__ __forceinline__ float geluf(float x) {
    return 0.5f * x * (1.0f + erff(x * 0.70710678118654752f));
}
static __device__ __forceinline__ float gelu_fast(float x) {
    float z = 0.7978845608f * fmaf(0.044715f, x * x * x, x);
    float e = __expf(2.f * z);
    float th = 1.f - __fdividef(2.f, e + 1.f);
    return 0.5f * x * (1.f + th);
}
static __device__ __forceinline__ float sigm(float x) {
    return 1.0f / (1.0f + __expf(-x));
}
static __device__ __forceinline__ __half2 fp8x2_h2(unsigned v) {
    __half2_raw hr = __nv_cvt_fp8x2_to_halfraw2((__nv_fp8x2_storage_t)(v & 0xffffu),
                                                __NV_E4M3);
    return *reinterpret_cast<__half2*>(&hr);
}
static __device__ __forceinline__ unsigned smem_u32(const void* p) {
    return (unsigned)__cvta_generic_to_shared(p);
}
static __device__ __forceinline__ void ldsm_x4(unsigned& r0, unsigned& r1,
                                               unsigned& r2, unsigned& r3, unsigned a) {
    asm volatile("ldmatrix.sync.aligned.m8n8.x4.shared.b16 {%0,%1,%2,%3}, [%4];"
                 : "=r"(r0), "=r"(r1), "=r"(r2), "=r"(r3) : "r"(a));
}
static __device__ __forceinline__ void ldsm_x2t(unsigned& r0, unsigned& r1, unsigned a) {
    asm volatile("ldmatrix.sync.aligned.m8n8.x2.trans.shared.b16 {%0,%1}, [%2];"
                 : "=r"(r0), "=r"(r1) : "r"(a));
}
static __device__ __forceinline__ void mma16816(float& c0, float& c1, float& c2, float& c3,
                                                unsigned a0, unsigned a1, unsigned a2, unsigned a3,
                                                unsigned b0, unsigned b1) {
    asm volatile("mma.sync.aligned.m16n8k16.row.col.f32.bf16.bf16.f32 "
                 "{%0,%1,%2,%3}, {%4,%5,%6,%7}, {%8,%9}, {%0,%1,%2,%3};"
                 : "+f"(c0), "+f"(c1), "+f"(c2), "+f"(c3)
                 : "r"(a0), "r"(a1), "r"(a2), "r"(a3), "r"(b0), "r"(b1));
}
static __device__ __forceinline__ void cp_async16(unsigned dst, const void* src) {
    asm volatile("cp.async.ca.shared.global [%0], [%1], 16;" :: "r"(dst), "l"(src));
}
static __device__ __forceinline__ void cp_commit() {
    asm volatile("cp.async.commit_group;");
}
static __device__ __forceinline__ void cp_wait0() {
    asm volatile("cp.async.wait_group 0;");
}
static __device__ __forceinline__ __nv_bfloat162 f2bf2(float a, float b) {
    return __floats2bfloat162_rn(a, b);
}

// ---------------------------------------------------------------------------
// Prep: 210 blocks x 256 threads
// ---------------------------------------------------------------------------
__global__ void prep_kernel(const float* __restrict__ ln_w, const float* __restrict__ ln_b,
                            const float* __restrict__ Wd,   const float* __restrict__ bd,
                            const float* __restrict__ Wq,   const float* __restrict__ Wk,
                            const float* __restrict__ Wv,   const float* __restrict__ Wg,
                            const float* __restrict__ Wu,
                            const float* __restrict__ cn1_w, const float* __restrict__ cn1_b,
                            const float* __restrict__ cn2_w, const float* __restrict__ cn2_b,
                            const float* __restrict__ dn1_w, const float* __restrict__ dn2_w) {
    int bi = blockIdx.x, tid = threadIdx.x;
    if (bi < 32) {
        int idx = bi * 256 + tid;            // d*32 + r
        g_Wdh[idx] = __float2bfloat16_rn(ln_w[idx >> 5] * Wd[idx]);
    } else if (bi < 48) {
        int idx = (bi - 32) * 256 + tid;     // kk*128 + o
        int kk = idx >> 7, o = idx & 127, m = o >> 5, r = o & 31;
        const float* src = (m == 0) ? Wq : (m == 1) ? Wk : (m == 2) ? Wv : Wg;
        g_W4h[idx] = __float2bfloat16_rn(src[kk * Rv + r]);
    } else if (bi < 80) {
        int idx = (bi - 48) * 256 + tid;     // r*256 + d
        g_Wuh[idx] = __float2bfloat16_rn(Wu[idx]);
    } else if (bi < 144) {
        int j = bi - 80;
        g_dn1f8[j * Dv + tid] =
            __nv_cvt_float_to_fp8(dn1_w[tid * Hv + j] * FP8S, __NV_SATFINITE, __NV_E4M3);
    } else if (bi < 208) {
        int j = bi - 144;
        g_dn2f8[j * Dv + tid] =
            __nv_cvt_float_to_fp8(dn2_w[j * Dv + tid] * FP8S, __NV_SATFINITE, __NV_E4M3);
    } else if (bi == 208) {
        __shared__ float ssw[8][32], slb[8][32];
        int r = tid & 31, seg = tid >> 5;
        float sw = 0.f, lb = 0.f;
        for (int dd = 0; dd < 32; dd++) {
            int d = seg * 32 + dd;
            float wv = Wd[d * Rv + r];
            sw += ln_w[d] * wv;
            lb += ln_b[d] * wv;
        }
        ssw[seg][r] = sw; slb[seg][r] = lb;
        __syncthreads();
        if (tid < 32) {
            float a = 0.f, b2 = 0.f;
            #pragma unroll
            for (int s = 0; s < 8; s++) { a += ssw[s][tid]; b2 += slb[s][tid]; }
            g_SW[tid] = a;
            g_LB[tid] = b2 + bd[tid];
        }
    } else {
        __shared__ float hid[Hv];
        const float lc = logf(21.0f) / logf(1000.0f);
        if (tid < Hv) hid[tid] = geluf(lc * cn1_w[tid] + cn1_b[tid]);
        __syncthreads();
        float acc = cn2_b[tid];
        for (int j = 0; j < Hv; j++) acc += hid[j] * cn2_w[j * Dv + tid];
        g_logits[tid] = acc;
    }
}

// ---------------------------------------------------------------------------
// Fully-fused kernel: one CTA per (b,p). 256 thr, 8 warps, 4 CTAs/SM.
// ---------------------------------------------------------------------------
__global__ __launch_bounds__(256, 4) void fused_kernel(
    const float* __restrict__ x,
    const float* __restrict__ bg,
    const float* __restrict__ bu,
    const float* __restrict__ dn1_b,
    const float* __restrict__ dn2_b,
    const float* __restrict__ eps_p,
    float* __restrict__ out)
{
    __shared__ __align__(16) __nv_bfloat16 h_b[32 * HB];    // x tile, later wu_b
    __shared__ __align__(16) __nv_bfloat16 wd_b[Dv * WB];   // Wd tile, later mixed
    __shared__ __align__(16) __nv_bfloat16 w4_b[Rv * W4B];  // W4 tile
    __shared__ __align__(16) __nv_bfloat16 A_b[32 * AB];    // qn*sig(g)
    __shared__ __align__(16) __nv_bfloat16 hl_b[32 * AB];   // h_low (junk rows 0)
    __shared__ __align__(16) float cvsred[2 * Dv];          // sred partials
    __shared__ __align__(16) __half cv_h[Dv];               // cv in half
    __shared__ float mu_s[32], rs_s[32];
    __shared__ __align__(16) float sw_s[32], lb_s[32];
    __shared__ __align__(16) float bg_s[32];
    __shared__ __align__(16) float gfp_s[2 * Rv];
    __shared__ __align__(16) __half hid_h[Hv];              // data-MLP hidden (half)
    __shared__ __align__(16) float gate_s[Dv];

    __nv_bfloat16* mixed_b = wd_b;   // wd_b dead after ph4; reuse for mixed

    const int tid = threadIdx.x;
    const int lane = tid & 31;
    const int w = tid >> 5;
    const int bp = blockIdx.x;
    const int bb = bp / Pv, pp = bp % Pv;
    const int xrow = bb * Cv * PDv + pp * Dv;

    if (tid < 32) {
        sw_s[tid] = g_SW[tid];
        lb_s[tid] = g_LB[tid];
        bg_s[tid] = __ldg(&bg[tid]);
    }
    if (tid >= 21 && tid < 32) { mu_s[tid] = 0.f; rs_s[tid] = 0.f; }

    // ---- R1: x -> h_b (bf16) + cv; cp.async stage Wd + W4 ----------------
    {
        float s1 = 0.f, s2 = 0.f;
        #pragma unroll
        for (int c = 0; c < Cv; c++) {
            float v = x[xrow + c * PDv + tid];
            h_b[c * HB + tid] = __float2bfloat16_rn(v);
            s1 += v; s2 += v * v;
        }
        cv_h[tid] = __float2half_rn((s2 - s1 * s1 * (1.0f / 21.0f)) * (1.0f / 20.0f));
    }
    {
        unsigned wdbase = smem_u32(wd_b);
        #pragma unroll
        for (int i = 0; i < 4; i++) {
            int idx = tid + 256 * i;            // 1024 chunks of 16B
            int row = idx >> 2, ch = idx & 3;
            cp_async16(wdbase + (unsigned)((row * WB + ch * 8) * 2),
                       g_Wdh + row * Rv + ch * 8);
        }
        unsigned w4base = smem_u32(w4_b);
        #pragma unroll
        for (int i = 0; i < 2; i++) {
            int idx = tid + 256 * i;            // 512 chunks
            int row = idx >> 4, ch = idx & 15;
            cp_async16(w4base + (unsigned)((row * W4B + ch * 8) * 2),
                       g_W4h + row * 128 + ch * 8);
        }
        cp_commit();
    }
    __syncthreads();

    // ---- R2: LN stats (packed s|ss reduce) + gate MLP1 (multi-value) -----
    #pragma unroll
    for (int ci = 0; ci < 3; ci++) {
        int c = w + 8 * ci;
        if (c < Cv) {
            float s = 0.f, ss = 0.f;
            #pragma unroll
            for (int k2 = 0; k2 < 4; k2++) {
                __nv_bfloat162 hv = *reinterpret_cast<const __nv_bfloat162*>(
                    &h_b[c * HB + 2 * lane + 64 * k2]);
                float2 f = __bfloat1622float2(hv);
                s += f.x + f.y; ss += f.x * f.x + f.y * f.y;
            }
            // pack: after xor16, lanes<16 carry s, lanes>=16 carry ss
            float sent = (lane & 16) ? s : ss;
            float recv = __shfl_xor_sync(0xffffffffu, sent, 16);
            float val = ((lane & 16) ? ss : s) + recv;
            #pragma unroll
            for (int o = 8; o > 0; o >>= 1)
                val += __shfl_xor_sync(0xffffffffu, val, o);
            float other = __shfl_xor_sync(0xffffffffu, val, 16);
            if (lane == 0) {
                float mu = val * (1.0f / 256.0f);
                float var = other * (1.0f / 256.0f) - mu * mu;
                mu_s[c] = mu;
                rs_s[c] = rsqrtf(var + 1e-5f);
            }
        }
    }
    {
        // lane owns d-range [8*lane, 8*lane+8) as 4 half2; 8 j per warp
        uint4 cvr = *reinterpret_cast<const uint4*>(&cv_h[8 * lane]);
        __half2 c0h = *reinterpret_cast<__half2*>(&cvr.x);
        __half2 c1h = *reinterpret_cast<__half2*>(&cvr.y);
        __half2 c2h = *reinterpret_cast<__half2*>(&cvr.z);
        __half2 c3h = *reinterpret_cast<__half2*>(&cvr.w);
        float p[8];
        #pragma unroll
        for (int jj = 0; jj < 8; jj++) {
            int j = w * 8 + jj;
            uint2 wv = __ldg(reinterpret_cast<const uint2*>(&g_dn1f8[j * Dv + 8 * lane]));
            __half2 acc = __hmul2(c3h, fp8x2_h2(wv.y >> 16));
            acc = __hfma2(c2h, fp8x2_h2(wv.y), acc);
            acc = __hfma2(c1h, fp8x2_h2(wv.x >> 16), acc);
            acc = __hfma2(c0h, fp8x2_h2(wv.x), acc);
            float2 pf = __half22float2(acc);
            p[jj] = pf.x + pf.y;
        }
        // multi-value butterfly: j = w*8 + 4*b16 + 2*b8 + b4
        #pragma unroll
        for (int i = 0; i < 4; i++) {
            float sent = (lane & 16) ? p[i] : p[i + 4];
            float recv = __shfl_xor_sync(0xffffffffu, sent, 16);
            p[i] = ((lane & 16) ? p[i + 4] : p[i]) + recv;
        }
        #pragma unroll
        for (int i = 0; i < 2; i++) {
            float sent = (lane & 8) ? p[i] : p[i + 2];
            float recv = __shfl_xor_sync(0xffffffffu, sent, 8);
            p[i] = ((lane & 8) ? p[i + 2] : p[i]) + recv;
        }
        {
            float sent = (lane & 4) ? p[0] : p[1];
            float recv = __shfl_xor_sync(0xffffffffu, sent, 4);
            p[0] = ((lane & 4) ? p[1] : p[0]) + recv;
        }
        p[0] += __shfl_xor_sync(0xffffffffu, p[0], 2);
        p[0] += __shfl_xor_sync(0xffffffffu, p[0], 1);
        if ((lane & 3) == 0) {
            int j = w * 8 + 4 * ((lane >> 4) & 1) + 2 * ((lane >> 3) & 1) + ((lane >> 2) & 1);
            float hv = gelu_fast(p[0] * FP8SI + __ldg(&dn1_b[j]));
            hid_h[j] = __float2half_rn(hv);
        }
    }
    cp_wait0();
    __syncthreads();

    // ---- R3: warps 0-3 ph4 MMA -> hl_b; warps 4-7 gate MLP2 (half2) ------
    if (w < 4) {
        const int mtile = w & 1;
        const int r0 = (w >> 1) * 16;
        const unsigned a_addr = smem_u32(h_b)
            + (unsigned)(((mtile * 16 + (lane & 15)) * HB + ((lane >> 4) << 3)) * 2);
        const unsigned b_addr0 = smem_u32(wd_b)
            + (unsigned)(((lane & 15) * WB + r0) * 2);
        const unsigned b_addr1 = b_addr0 + 16;
        float c0[4] = {0.f, 0.f, 0.f, 0.f};
        float c1[4] = {0.f, 0.f, 0.f, 0.f};
        #pragma unroll
        for (int k = 0; k < 16; k++) {
            unsigned a0, a1, a2, a3, b0, b1;
            ldsm_x4(a0, a1, a2, a3, a_addr + k * 32);
            ldsm_x2t(b0, b1, b_addr0 + k * 16 * WB * 2);
            mma16816(c0[0], c0[1], c0[2], c0[3], a0, a1, a2, a3, b0, b1);
            ldsm_x2t(b0, b1, b_addr1 + k * 16 * WB * 2);
            mma16816(c1[0], c1[1], c1[2], c1[3], a0, a1, a2, a3, b0, b1);
        }
        const int m0 = mtile * 16 + (lane >> 2);
        const int m1 = m0 + 8;
        const bool v0 = m0 < Cv, v1 = m1 < Cv;
        const float mu0 = mu_s[m0], rv0 = rs_s[m0];
        const float mu1 = mu_s[m1], rv1 = rs_s[m1];
        #pragma unroll
        for (int nt = 0; nt < 2; nt++) {
            const float* cc = nt ? c1 : c0;
            int col = r0 + nt * 8 + 2 * (lane & 3);
            float sw0 = sw_s[col], sw1 = sw_s[col + 1];
            float lb0 = lb_s[col], lb1 = lb_s[col + 1];
            float h00 = v0 ? (rv0 * (cc[0] - mu0 * sw0) + lb0) : 0.f;
            float h01 = v0 ? (rv0 * (cc[1] - mu0 * sw1) + lb1) : 0.f;
            float h10 = v1 ? (rv1 * (cc[2] - mu1 * sw0) + lb0) : 0.f;
            float h11 = v1 ? (rv1 * (cc[3] - mu1 * sw1) + lb1) : 0.f;
            *reinterpret_cast<__nv_bfloat162*>(&hl_b[m0 * AB + col]) = f2bf2(h00, h01);
            *reinterpret_cast<__nv_bfloat162*>(&hl_b[m1 * AB + col]) = f2bf2(h10, h11);
        }
    } else {
        const int local = tid - 128;
        const int dq = local & 63;            // d = 4dq .. 4dq+3
        const int jh = local >> 6;
        __half2 acc01 = __float2half2_rn(0.f), acc23 = acc01;
        #pragma unroll
        for (int j4 = 0; j4 < 8; j4++) {
            int j = 32 * jh + 4 * j4;
            uint2 hraw = *reinterpret_cast<const uint2*>(&hid_h[j]);
            __half2 hp01 = *reinterpret_cast<__half2*>(&hraw.x);
            __half2 hp23 = *reinterpret_cast<__half2*>(&hraw.y);
            #pragma unroll
            for (int t = 0; t < 4; t++) {
                unsigned wv = __ldg(reinterpret_cast<const unsigned*>(
                    &g_dn2f8[(j + t) * Dv + 4 * dq]));
                __half hj = (t == 0) ? __low2half(hp01) : (t == 1) ? __high2half(hp01)
                          : (t == 2) ? __low2half(hp23) : __high2half(hp23);
                __half2 hb = __half2half2(hj);
                acc01 = __hfma2(hb, fp8x2_h2(wv), acc01);
                acc23 = __hfma2(hb, fp8x2_h2(wv >> 16), acc23);
            }
        }
        float2 f01 = __half22float2(acc01);
        float2 f23 = __half22float2(acc23);
        *reinterpret_cast<float4*>(&cvsred[jh * Dv + 4 * dq]) =
            make_float4(f01.x, f01.y, f23.x, f23.y);
    }
    __syncthreads();

    // ---- R4: warps 0-3 ph5 MMA (QKVG); warps 4-7 gate finalize + Wu stage
    if (w < 4) {
        const int role = w & 1;      // 0: q&g, 1: k&v
        const int mt = w >> 1;
        const unsigned a_addr = smem_u32(hl_b)
            + (unsigned)(((mt * 16 + (lane & 15)) * AB + ((lane >> 4) << 3)) * 2);
        unsigned a0, a1, a2, a3, a4, a5, a6, a7;
        ldsm_x4(a0, a1, a2, a3, a_addr);
        ldsm_x4(a4, a5, a6, a7, a_addr + 32);
        const int ob1 = role ? 32 : 0;    // k : q
        const int ob2 = role ? 64 : 96;   // v : g
        const unsigned bbase = smem_u32(w4_b) + (unsigned)(((lane & 15) * W4B) * 2);
        const unsigned bk16 = 16 * W4B * 2;
        float c1v[16], c2v[16];
        #pragma unroll
        for (int i = 0; i < 16; i++) { c1v[i] = 0.f; c2v[i] = 0.f; }
        #pragma unroll
        for (int nb = 0; nb < 4; nb++) {
            unsigned b0, b1;
            ldsm_x2t(b0, b1, bbase + (ob1 + nb * 8) * 2);
            mma16816(c1v[4*nb], c1v[4*nb+1], c1v[4*nb+2], c1v[4*nb+3],
                     a0, a1, a2, a3, b0, b1);
            ldsm_x2t(b0, b1, bbase + bk16 + (ob1 + nb * 8) * 2);
            mma16816(c1v[4*nb], c1v[4*nb+1], c1v[4*nb+2], c1v[4*nb+3],
                     a4, a5, a6, a7, b0, b1);
            ldsm_x2t(b0, b1, bbase + (ob2 + nb * 8) * 2);
            mma16816(c2v[4*nb], c2v[4*nb+1], c2v[4*nb+2], c2v[4*nb+3],
                     a0, a1, a2, a3, b0, b1);
            ldsm_x2t(b0, b1, bbase + bk16 + (ob2 + nb * 8) * 2);
            mma16816(c2v[4*nb], c2v[4*nb+1], c2v[4*nb+2], c2v[4*nb+3],
                     a4, a5, a6, a7, b0, b1);
        }
        float qs0 = 0.f, qs1 = 0.f;
        #pragma unroll
        for (int nb = 0; nb < 4; nb++) {
            qs0 += c1v[4*nb] * c1v[4*nb] + c1v[4*nb+1] * c1v[4*nb+1];
            qs1 += c1v[4*nb+2] * c1v[4*nb+2] + c1v[4*nb+3] * c1v[4*nb+3];
        }
        qs0 += __shfl_xor_sync(0xffffffffu, qs0, 1);
        qs0 += __shfl_xor_sync(0xffffffffu, qs0, 2);
        qs1 += __shfl_xor_sync(0xffffffffu, qs1, 1);
        qs1 += __shfl_xor_sync(0xffffffffu, qs1, 2);
        float rn0 = rsqrtf(fmaxf(qs0, 1e-24f));
        float rn1 = rsqrtf(fmaxf(qs1, 1e-24f));
        if (role == 0) {
            const int m0 = mt * 16 + (lane >> 2);
            const int m1 = m0 + 8;
            #pragma unroll
            for (int nb = 0; nb < 4; nb++) {
                int rcol = nb * 8 + 2 * (lane & 3);
                float2 bgv = *reinterpret_cast<const float2*>(&bg_s[rcol]);
                float A0 = c1v[4*nb]   * rn0 * sigm(c2v[4*nb]   + bgv.x);
                float A1 = c1v[4*nb+1] * rn0 * sigm(c2v[4*nb+1] + bgv.y);
                float A2 = c1v[4*nb+2] * rn1 * sigm(c2v[4*nb+2] + bgv.x);
                float A3 = c1v[4*nb+3] * rn1 * sigm(c2v[4*nb+3] + bgv.y);
                *reinterpret_cast<__nv_bfloat162*>(&A_b[m0 * AB + rcol]) = f2bf2(A0, A1);
                *reinterpret_cast<__nv_bfloat162*>(&A_b[m1 * AB + rcol]) = f2bf2(A2, A3);
            }
        } else {
            // gf partials: p[v], v = nb*2 + col; butterfly over hops 4,8,16
            float p[8];
            #pragma unroll
            for (int nb = 0; nb < 4; nb++) {
                p[2*nb]   = c1v[4*nb]   * rn0 * c2v[4*nb]   + c1v[4*nb+2] * rn1 * c2v[4*nb+2];
                p[2*nb+1] = c1v[4*nb+1] * rn0 * c2v[4*nb+1] + c1v[4*nb+3] * rn1 * c2v[4*nb+3];
            }
            #pragma unroll
            for (int i = 0; i < 4; i++) {
                float sent = (lane & 4) ? p[i] : p[i + 4];
                float recv = __shfl_xor_sync(0xffffffffu, sent, 4);
                p[i] = ((lane & 4) ? p[i + 4] : p[i]) + recv;
            }
            #pragma unroll
            for (int i = 0; i < 2; i++) {
                float sent = (lane & 8) ? p[i] : p[i + 2];
                float recv = __shfl_xor_sync(0xffffffffu, sent, 8);
                p[i] = ((lane & 8) ? p[i + 2] : p[i]) + recv;
            }
            {
                float sent = (lane & 16) ? p[0] : p[1];
                float recv = __shfl_xor_sync(0xffffffffu, sent, 16);
                p[0] = ((lane & 16) ? p[1] : p[0]) + recv;
            }
            // v = 4*b4 + 2*b8 + b16 -> nb = 2*b4 + b8, col = b16
            int nb = 2 * ((lane >> 2) & 1) + ((lane >> 3) & 1);
            int col = (lane >> 4) & 1;
            gfp_s[mt * 32 + nb * 8 + 2 * (lane & 3) + col] = p[0];
        }
    } else {
        // gate finalize: 2 d per thread
        const int local = tid - 128;
        const float ev = __ldg(eps_p);
        #pragma unroll
        for (int t = 0; t < 2; t++) {
            int dd = 2 * local + t;
            float dc = (cvsred[dd] + cvsred[Dv + dd]) * FP8SI;
            gate_s[dd] = sigm(__ldg(&g_logits[dd]) + ev * (dc + __ldg(&dn2_b[dd])));
        }
        // cp.async stage Wu into h_b (dead after ph4)
        unsigned wubase = smem_u32(h_b);
        #pragma unroll
        for (int i = 0; i < 8; i++) {
            int idx = local + 128 * i;           // 1024 chunks
            int row = idx >> 5, ch = idx & 31;
            cp_async16(wubase + (unsigned)((row * HB + ch * 8) * 2),
                       g_Wuh + row * Dv + ch * 8);
        }
        cp_commit();
        cp_wait0();
    }
    __syncthreads();   // gfp_s, gate_s, A_b, wu_b all ready

    // ---- R6: ph6 MMA ((A*gf) @ wu_b) -> mixed_b (gf computed inline) -----
    {
        const int mtile = w & 1;
        const int nb0 = (w >> 1) * 64;
        const unsigned a_addr = smem_u32(A_b)
            + (unsigned)(((mtile * 16 + (lane & 15)) * AB + ((lane >> 4) << 3)) * 2);
        unsigned a00, a01, a02, a03, a10, a11, a12, a13;
        ldsm_x4(a00, a01, a02, a03, a_addr);
        ldsm_x4(a10, a11, a12, a13, a_addr + 32);
        {
            int kc2 = 2 * (lane & 3);
            float2 p, q2;
            p = *reinterpret_cast<const float2*>(&gfp_s[kc2]);
            q2 = *reinterpret_cast<const float2*>(&gfp_s[32 + kc2]);
            __nv_bfloat162 s0 = f2bf2(p.x + q2.x, p.y + q2.y);
            p = *reinterpret_cast<const float2*>(&gfp_s[kc2 + 8]);
            q2 = *reinterpret_cast<const float2*>(&gfp_s[40 + kc2]);
            __nv_bfloat162 s1 = f2bf2(p.x + q2.x, p.y + q2.y);
            p = *reinterpret_cast<const float2*>(&gfp_s[kc2 + 16]);
            q2 = *reinterpret_cast<const float2*>(&gfp_s[48 + kc2]);
            __nv_bfloat162 s2 = f2bf2(p.x + q2.x, p.y + q2.y);
            p = *reinterpret_cast<const float2*>(&gfp_s[kc2 + 24]);
            q2 = *reinterpret_cast<const float2*>(&gfp_s[56 + kc2]);
            __nv_bfloat162 s3 = f2bf2(p.x + q2.x, p.y + q2.y);
            __nv_bfloat162* pa;
            pa = reinterpret_cast<__nv_bfloat162*>(&a00); *pa = __hmul2(*pa, s0);
            pa = reinterpret_cast<__nv_bfloat162*>(&a01); *pa = __hmul2(*pa, s0);
            pa = reinterpret_cast<__nv_bfloat162*>(&a02); *pa = __hmul2(*pa, s1);
            pa = reinterpret_cast<__nv_bfloat162*>(&a03); *pa = __hmul2(*pa, s1);
            pa = reinterpret_cast<__nv_bfloat162*>(&a10); *pa = __hmul2(*pa, s2);
            pa = reinterpret_cast<__nv_bfloat162*>(&a11); *pa = __hmul2(*pa, s2);
            pa = reinterpret_cast<__nv_bfloat162*>(&a12); *pa = __hmul2(*pa, s3);
            pa = reinterpret_cast<__nv_bfloat162*>(&a13); *pa = __hmul2(*pa, s3);
        }
        const unsigned b_base = smem_u32(h_b) + (unsigned)(((lane & 15) * HB) * 2);
        const int m0 = mtile * 16 + (lane >> 2);
        const int m1 = m0 + 8;
        #pragma unroll
        for (int t = 0; t < 8; t++) {
            int n0 = nb0 + t * 8;
            unsigned b0, b1, b2, b3;
            ldsm_x2t(b0, b1, b_base + n0 * 2);
            ldsm_x2t(b2, b3, b_base + 16 * HB * 2 + n0 * 2);
            float c0 = 0.f, c1 = 0.f, c2 = 0.f, c3 = 0.f;
            mma16816(c0, c1, c2, c3, a00, a01, a02, a03, b0, b1);
            mma16816(c0, c1, c2, c3, a10, a11, a12, a13, b2, b3);
            int d0 = n0 + 2 * (lane & 3);
            if (m0 < Cv)
                *reinterpret_cast<__nv_bfloat162*>(&mixed_b[m0 * MB + d0]) = f2bf2(c0, c1);
            if (m1 < Cv)
                *reinterpret_cast<__nv_bfloat162*>(&mixed_b[m1 * MB + d0]) = f2bf2(c2, c3);
        }
    }
    __syncthreads();

    // ---- R7: vectorized out = x + gate*(mixed + bu) ----------------------
    {
        const int col0 = 4 * (tid & 63);
        const int rg = tid >> 6;
        float4 gv4 = *reinterpret_cast<const float4*>(&gate_s[col0]);
        float4 bu4 = __ldg(reinterpret_cast<const float4*>(&bu[col0]));
        #pragma unroll
        for (int k = 0; k < 6; k++) {
            int c = rg + 4 * k;
            if (c < Cv) {
                uint2 mm = *reinterpret_cast<const uint2*>(&mixed_b[c * MB + col0]);
                float2 f01 = __bfloat1622float2(*reinterpret_cast<__nv_bfloat162*>(&mm.x));
                float2 f23 = __bfloat1622float2(*reinterpret_cast<__nv_bfloat162*>(&mm.y));
                int gi = xrow + c * PDv + col0;
                float4 xv = *reinterpret_cast<const float4*>(&x[gi]);
                float4 o;
                o.x = xv.x + gv4.x * (f01.x + bu4.x);
                o.y = xv.y + gv4.y * (f01.y + bu4.y);
                o.z = xv.z + gv4.z * (f23.x + bu4.z);
                o.w = xv.w + gv4.w * (f23.y + bu4.w);
                *reinterpret_cast<float4*>(&out[gi]) = o;
            }
        }
    }
}

// ---------------------------------------------------------------------------
extern "C" void kernel_launch(void* const* d_in, const int* in_sizes, int n_in,
                              void* d_out, int out_size) {
    const float* x     = (const float*)d_in[0];
    const float* ln_w  = (const float*)d_in[1];
    const float* ln_b  = (const float*)d_in[2];
    const float* Wd    = (const float*)d_in[3];
    const float* bd    = (const float*)d_in[4];
    const float* Wq    = (const float*)d_in[5];
    const float* Wk    = (const float*)d_in[6];
    const float* Wvp   = (const float*)d_in[7];
    const float* Wg    = (const float*)d_in[8];
    const float* bg    = (const float*)d_in[9];
    const float* Wu    = (const float*)d_in[10];
    const float* bu    = (const float*)d_in[11];
    const float* cn1_w = (const float*)d_in[12];
    const float* cn1_b = (const float*)d_in[13];
    const float* cn2_w = (const float*)d_in[14];
    const float* cn2_b = (const float*)d_in[15];
    const float* dn1_w = (const float*)d_in[16];
    const float* dn1_b = (const float*)d_in[17];
    const float* dn2_w = (const float*)d_in[18];
    const float* dn2_b = (const float*)d_in[19];
    const float* eps   = (const float*)d_in[20];
    float* out = (float*)d_out;

    prep_kernel<<<210, 256>>>(ln_w, ln_b, Wd, bd, Wq, Wk, Wvp, Wg, Wu,
                              cn1_w, cn1_b, cn2_w, cn2_b, dn1_w, dn2_w);
    fused_kernel<<<BPv, 256>>>(x, bg, bu, dn1_b, dn2_b, eps, out);
}

// round 17
// speedup vs baseline: 1.6359x; 1.0476x over previous
#include <cuda_runtime.h>
#include <cuda_bf16.h>
#include <cuda_fp16.h>
#include <cuda_fp8.h>
#include <math.h>

#define Bv 64
#define Cv 21
#define Pv 96
#define Dv 256
#define Rv 32
#define Hv 64
#define BPv (Bv*Pv)
#define PDv (Pv*Dv)

// padded smem strides (elements); all 16B multiples with odd-16B rotation
#define HB  264   // h_b / wu_b row stride (528B)
#define WB  40    // wd_b row stride (80B)
#define AB  40    // A_b / hl_b row stride (80B)
#define W4B 136   // w4_b row stride (272B)
#define MB  264   // mixed row stride

#define FP8S 32.0f
#define FP8SI (1.0f/32.0f)

// ---------------- device-global precomputed weights -------------------------
__device__ __align__(16) __nv_bfloat16 g_Wdh[Dv*Rv];        // [d][r] = bf16(ln_w*Wd)
__device__ __align__(16) __nv_bfloat16 g_W4h[Rv*128];       // [kk][o]
__device__ __align__(16) __nv_bfloat16 g_Wuh[Rv*Dv];        // [r][d]
__device__ __align__(16) __nv_fp8_storage_t g_dn1f8[Hv*Dv]; // [j][d]
__device__ __align__(16) __nv_fp8_storage_t g_dn2f8[Hv*Dv]; // [j][d]
__device__ float g_SW[Rv];
__device__ float g_LB[Rv];
__device__ float g_logits[Dv];

static __device__ __forceinline__ float geluf(float x) {
    return 0.5f * x * (1.0f + erff(x * 0.70710678118654752f));
}
static __device__ __forceinline__ float tanh_a(float x) {
    float r;
    asm("tanh.approx.f32 %0, %1;" : "=f"(r) : "f"(x));
    return r;
}
static __device__ __forceinline__ float gelu_fast(float x) {
    float z = 0.7978845608f * fmaf(0.044715f, x * x * x, x);
    return 0.5f * x * (1.f + tanh_a(z));
}
static __device__ __forceinline__ float sigm(float x) {          // accurate (gate path)
    return 1.0f / (1.0f + __expf(-x));
}
static __device__ __forceinline__ float sigm_fast(float x) {     // tanh.approx (A path)
    return fmaf(0.5f, tanh_a(0.5f * x), 0.5f);
}
static __device__ __forceinline__ __half2 fp8x2_h2(unsigned v) {
    __half2_raw hr = __nv_cvt_fp8x2_to_halfraw2((__nv_fp8x2_storage_t)(v & 0xffffu),
                                                __NV_E4M3);
    return *reinterpret_cast<__half2*>(&hr);
}
static __device__ __forceinline__ unsigned smem_u32(const void* p) {
    return (unsigned)__cvta_generic_to_shared(p);
}
static __device__ __forceinline__ void ldsm_x4(unsigned& r0, unsigned& r1,
                                               unsigned& r2, unsigned& r3, unsigned a) {
    asm volatile("ldmatrix.sync.aligned.m8n8.x4.shared.b16 {%0,%1,%2,%3}, [%4];"
                 : "=r"(r0), "=r"(r1), "=r"(r2), "=r"(r3) : "r"(a));
}
static __device__ __forceinline__ void ldsm_x2t(unsigned& r0, unsigned& r1, unsigned a) {
    asm volatile("ldmatrix.sync.aligned.m8n8.x2.trans.shared.b16 {%0,%1}, [%2];"
                 : "=r"(r0), "=r"(r1) : "r"(a));
}
static __device__ __forceinline__ void mma16816(float& c0, float& c1, float& c2, float& c3,
                                                unsigned a0, unsigned a1, unsigned a2, unsigned a3,
                                                unsigned b0, unsigned b1) {
    asm volatile("mma.sync.aligned.m16n8k16.row.col.f32.bf16.bf16.f32 "
                 "{%0,%1,%2,%3}, {%4,%5,%6,%7}, {%8,%9}, {%0,%1,%2,%3};"
                 : "+f"(c0), "+f"(c1), "+f"(c2), "+f"(c3)
                 : "r"(a0), "r"(a1), "r"(a2), "r"(a3), "r"(b0), "r"(b1));
}
static __device__ __forceinline__ void cp_async16(unsigned dst, const void* src) {
    asm volatile("cp.async.ca.shared.global [%0], [%1], 16;" :: "r"(dst), "l"(src));
}
static __device__ __forceinline__ void cp_commit() {
    asm volatile("cp.async.commit_group;");
}
static __device__ __forceinline__ void cp_wait0() {
    asm volatile("cp.async.wait_group 0;");
}
static __device__ __forceinline__ __nv_bfloat162 f2bf2(float a, float b) {
    return __floats2bfloat162_rn(a, b);
}

// ---------------------------------------------------------------------------
// Prep: 210 blocks x 256 threads
// ---------------------------------------------------------------------------
__global__ void prep_kernel(const float* __restrict__ ln_w, const float* __restrict__ ln_b,
                            const float* __restrict__ Wd,   const float* __restrict__ bd,
                            const float* __restrict__ Wq,   const float* __restrict__ Wk,
                            const float* __restrict__ Wv,   const float* __restrict__ Wg,
                            const float* __restrict__ Wu,
                            const float* __restrict__ cn1_w, const float* __restrict__ cn1_b,
                            const float* __restrict__ cn2_w, const float* __restrict__ cn2_b,
                            const float* __restrict__ dn1_w, const float* __restrict__ dn2_w) {
    int bi = blockIdx.x, tid = threadIdx.x;
    if (bi < 32) {
        int idx = bi * 256 + tid;            // d*32 + r
        g_Wdh[idx] = __float2bfloat16_rn(ln_w[idx >> 5] * Wd[idx]);
    } else if (bi < 48) {
        int idx = (bi - 32) * 256 + tid;     // kk*128 + o
        int kk = idx >> 7, o = idx & 127, m = o >> 5, r = o & 31;
        const float* src = (m == 0) ? Wq : (m == 1) ? Wk : (m == 2) ? Wv : Wg;
        g_W4h[idx] = __float2bfloat16_rn(src[kk * Rv + r]);
    } else if (bi < 80) {
        int idx = (bi - 48) * 256 + tid;     // r*256 + d
        g_Wuh[idx] = __float2bfloat16_rn(Wu[idx]);
    } else if (bi < 144) {
        int j = bi - 80;
        g_dn1f8[j * Dv + tid] =
            __nv_cvt_float_to_fp8(dn1_w[tid * Hv + j] * FP8S, __NV_SATFINITE, __NV_E4M3);
    } else if (bi < 208) {
        int j = bi - 144;
        g_dn2f8[j * Dv + tid] =
            __nv_cvt_float_to_fp8(dn2_w[j * Dv + tid] * FP8S, __NV_SATFINITE, __NV_E4M3);
    } else if (bi == 208) {
        __shared__ float ssw[8][32], slb[8][32];
        int r = tid & 31, seg = tid >> 5;
        float sw = 0.f, lb = 0.f;
        for (int dd = 0; dd < 32; dd++) {
            int d = seg * 32 + dd;
            float wv = Wd[d * Rv + r];
            sw += ln_w[d] * wv;
            lb += ln_b[d] * wv;
        }
        ssw[seg][r] = sw; slb[seg][r] = lb;
        __syncthreads();
        if (tid < 32) {
            float a = 0.f, b2 = 0.f;
            #pragma unroll
            for (int s = 0; s < 8; s++) { a += ssw[s][tid]; b2 += slb[s][tid]; }
            g_SW[tid] = a;
            g_LB[tid] = b2 + bd[tid];
        }
    } else {
        __shared__ float hid[Hv];
        const float lc = logf(21.0f) / logf(1000.0f);
        if (tid < Hv) hid[tid] = geluf(lc * cn1_w[tid] + cn1_b[tid]);
        __syncthreads();
        float acc = cn2_b[tid];
        for (int j = 0; j < Hv; j++) acc += hid[j] * cn2_w[j * Dv + tid];
        g_logits[tid] = acc;
    }
}

// ---------------------------------------------------------------------------
// Fully-fused kernel: one CTA per (b,p). 256 thr, 8 warps, 4 CTAs/SM.
// ---------------------------------------------------------------------------
__global__ __launch_bounds__(256, 4) void fused_kernel(
    const float* __restrict__ x,
    const float* __restrict__ bg,
    const float* __restrict__ bu,
    const float* __restrict__ dn1_b,
    const float* __restrict__ dn2_b,
    const float* __restrict__ eps_p,
    float* __restrict__ out)
{
    __shared__ __align__(16) __nv_bfloat16 h_b[32 * HB];    // x tile, later wu_b
    __shared__ __align__(16) __nv_bfloat16 wd_b[Dv * WB];   // Wd tile, later mixed
    __shared__ __align__(16) __nv_bfloat16 w4_b[Rv * W4B];  // W4 tile
    __shared__ __align__(16) __nv_bfloat16 A_b[32 * AB];    // qn*sig(g)
    __shared__ __align__(16) __nv_bfloat16 hl_b[32 * AB];   // h_low (junk rows 0)
    __shared__ __align__(16) float cvsred[2 * Dv];          // sred partials
    __shared__ __align__(16) __half cv_h[Dv];               // cv in half
    __shared__ float mu_s[32], rs_s[32];
    __shared__ __align__(16) float sw_s[32], lb_s[32];
    __shared__ __align__(16) float bg_s[32];
    __shared__ __align__(16) float gfp_s[2 * Rv];
    __shared__ __align__(16) __half hid_h[Hv];              // data-MLP hidden (half)
    __shared__ __align__(16) float gate_s[Dv];

    __nv_bfloat16* mixed_b = wd_b;   // wd_b dead after ph4; reuse for mixed

    const int tid = threadIdx.x;
    const int lane = tid & 31;
    const int w = tid >> 5;
    const int bp = blockIdx.x;
    const int bb = bp / Pv, pp = bp % Pv;
    const int xrow = bb * Cv * PDv + pp * Dv;

    if (tid < 32) {
        sw_s[tid] = g_SW[tid];
        lb_s[tid] = g_LB[tid];
        bg_s[tid] = __ldg(&bg[tid]);
    }
    if (tid >= 21 && tid < 32) { mu_s[tid] = 0.f; rs_s[tid] = 0.f; }

    // ---- R1: x -> h_b (bf16) + cv; cp.async stage Wd + W4 ----------------
    {
        float s1 = 0.f, s2 = 0.f;
        #pragma unroll
        for (int c = 0; c < Cv; c++) {
            float v = x[xrow + c * PDv + tid];
            h_b[c * HB + tid] = __float2bfloat16_rn(v);
            s1 += v; s2 += v * v;
        }
        cv_h[tid] = __float2half_rn((s2 - s1 * s1 * (1.0f / 21.0f)) * (1.0f / 20.0f));
    }
    {
        unsigned wdbase = smem_u32(wd_b);
        #pragma unroll
        for (int i = 0; i < 4; i++) {
            int idx = tid + 256 * i;            // 1024 chunks of 16B
            int row = idx >> 2, ch = idx & 3;
            cp_async16(wdbase + (unsigned)((row * WB + ch * 8) * 2),
                       g_Wdh + row * Rv + ch * 8);
        }
        unsigned w4base = smem_u32(w4_b);
        #pragma unroll
        for (int i = 0; i < 2; i++) {
            int idx = tid + 256 * i;            // 512 chunks
            int row = idx >> 4, ch = idx & 15;
            cp_async16(w4base + (unsigned)((row * W4B + ch * 8) * 2),
                       g_W4h + row * 128 + ch * 8);
        }
        cp_commit();
    }
    __syncthreads();

    // ---- R2: LN stats (multi-value butterfly) + gate MLP1 (multi-value) --
    {
        // accumulate s/ss for channels c = w, w+8, w+16 (if valid)
        float p[8];
        #pragma unroll
        for (int i = 0; i < 8; i++) p[i] = 0.f;
        #pragma unroll
        for (int ci = 0; ci < 3; ci++) {
            int c = w + 8 * ci;
            if (c < Cv) {
                float s = 0.f, ss = 0.f;
                #pragma unroll
                for (int k2 = 0; k2 < 4; k2++) {
                    __nv_bfloat162 hv = *reinterpret_cast<const __nv_bfloat162*>(
                        &h_b[c * HB + 2 * lane + 64 * k2]);
                    float2 f = __bfloat1622float2(hv);
                    s += f.x + f.y; ss += f.x * f.x + f.y * f.y;
                }
                // value index v = b4 + 2*b8 + 4*b16 : stat=b4, channel k=(b8,b16)
                p[2 * ci]     = s;    // v = 2k   (b4=0)
                p[2 * ci + 1] = ss;   // v = 2k+1 (b4=1)
            }
        }
        // reorder p[] to v = b4 + 2*b8 + 4*b16 indexing: p[i] where
        // i bit0->b4, bit1->b8, bit2->b16. p[2k]=s_k / p[2k+1]=ss_k maps to
        // v: k = b8 + 2*b16, stat = b4 -> index = stat + 2*k. Same layout. OK.
        #pragma unroll
        for (int i = 0; i < 4; i++) {
            float sent = (lane & 16) ? p[i] : p[i + 4];
            float recv = __shfl_xor_sync(0xffffffffu, sent, 16);
            p[i] = ((lane & 16) ? p[i + 4] : p[i]) + recv;
        }
        #pragma unroll
        for (int i = 0; i < 2; i++) {
            float sent = (lane & 8) ? p[i] : p[i + 2];
            float recv = __shfl_xor_sync(0xffffffffu, sent, 8);
            p[i] = ((lane & 8) ? p[i + 2] : p[i]) + recv;
        }
        {
            float sent = (lane & 4) ? p[0] : p[1];
            float recv = __shfl_xor_sync(0xffffffffu, sent, 4);
            p[0] = ((lane & 4) ? p[1] : p[0]) + recv;
        }
        p[0] += __shfl_xor_sync(0xffffffffu, p[0], 2);
        p[0] += __shfl_xor_sync(0xffffffffu, p[0], 1);
        // lane holds total of value v = b4 + 2*b8 + 4*b16; pair s with ss
        float other = __shfl_xor_sync(0xffffffffu, p[0], 4);
        if (lane == 0 || lane == 8 || lane == 16) {   // b4=0, low bits 0
            int k = ((lane >> 3) & 1) + 2 * ((lane >> 4) & 1);
            int c = w + 8 * k;
            if (c < Cv) {
                float mu = p[0] * (1.0f / 256.0f);
                float var = other * (1.0f / 256.0f) - mu * mu;
                mu_s[c] = mu;
                rs_s[c] = rsqrtf(var + 1e-5f);
            }
        }
    }
    {
        // gate MLP1: lane owns d-range [8*lane, 8*lane+8); 8 j per warp
        uint4 cvr = *reinterpret_cast<const uint4*>(&cv_h[8 * lane]);
        __half2 c0h = *reinterpret_cast<__half2*>(&cvr.x);
        __half2 c1h = *reinterpret_cast<__half2*>(&cvr.y);
        __half2 c2h = *reinterpret_cast<__half2*>(&cvr.z);
        __half2 c3h = *reinterpret_cast<__half2*>(&cvr.w);
        float p[8];
        #pragma unroll
        for (int jj = 0; jj < 8; jj++) {
            int j = w * 8 + jj;
            uint2 wv = __ldg(reinterpret_cast<const uint2*>(&g_dn1f8[j * Dv + 8 * lane]));
            __half2 acc = __hmul2(c3h, fp8x2_h2(wv.y >> 16));
            acc = __hfma2(c2h, fp8x2_h2(wv.y), acc);
            acc = __hfma2(c1h, fp8x2_h2(wv.x >> 16), acc);
            acc = __hfma2(c0h, fp8x2_h2(wv.x), acc);
            float2 pf = __half22float2(acc);
            p[jj] = pf.x + pf.y;
        }
        // multi-value butterfly: j = w*8 + 4*b16 + 2*b8 + b4
        #pragma unroll
        for (int i = 0; i < 4; i++) {
            float sent = (lane & 16) ? p[i] : p[i + 4];
            float recv = __shfl_xor_sync(0xffffffffu, sent, 16);
            p[i] = ((lane & 16) ? p[i + 4] : p[i]) + recv;
        }
        #pragma unroll
        for (int i = 0; i < 2; i++) {
            float sent = (lane & 8) ? p[i] : p[i + 2];
            float recv = __shfl_xor_sync(0xffffffffu, sent, 8);
            p[i] = ((lane & 8) ? p[i + 2] : p[i]) + recv;
        }
        {
            float sent = (lane & 4) ? p[0] : p[1];
            float recv = __shfl_xor_sync(0xffffffffu, sent, 4);
            p[0] = ((lane & 4) ? p[1] : p[0]) + recv;
        }
        p[0] += __shfl_xor_sync(0xffffffffu, p[0], 2);
        p[0] += __shfl_xor_sync(0xffffffffu, p[0], 1);
        if ((lane & 3) == 0) {
            int j = w * 8 + 4 * ((lane >> 4) & 1) + 2 * ((lane >> 3) & 1) + ((lane >> 2) & 1);
            float hv = gelu_fast(p[0] * FP8SI + __ldg(&dn1_b[j]));
            hid_h[j] = __float2half_rn(hv);
        }
    }
    cp_wait0();
    __syncthreads();

    // ---- R3: warps 0-3 ph4 MMA -> hl_b; warps 4-7 gate MLP2 (half2) ------
    if (w < 4) {
        const int mtile = w & 1;
        const int r0 = (w >> 1) * 16;
        const unsigned a_addr = smem_u32(h_b)
            + (unsigned)(((mtile * 16 + (lane & 15)) * HB + ((lane >> 4) << 3)) * 2);
        const unsigned b_addr0 = smem_u32(wd_b)
            + (unsigned)(((lane & 15) * WB + r0) * 2);
        const unsigned b_addr1 = b_addr0 + 16;
        float c0[4] = {0.f, 0.f, 0.f, 0.f};
        float c1[4] = {0.f, 0.f, 0.f, 0.f};
        #pragma unroll
        for (int k = 0; k < 16; k++) {
            unsigned a0, a1, a2, a3, b0, b1;
            ldsm_x4(a0, a1, a2, a3, a_addr + k * 32);
            ldsm_x2t(b0, b1, b_addr0 + k * 16 * WB * 2);
            mma16816(c0[0], c0[1], c0[2], c0[3], a0, a1, a2, a3, b0, b1);
            ldsm_x2t(b0, b1, b_addr1 + k * 16 * WB * 2);
            mma16816(c1[0], c1[1], c1[2], c1[3], a0, a1, a2, a3, b0, b1);
        }
        const int m0 = mtile * 16 + (lane >> 2);
        const int m1 = m0 + 8;
        const bool v0 = m0 < Cv, v1 = m1 < Cv;
        const float mu0 = mu_s[m0], rv0 = rs_s[m0];
        const float mu1 = mu_s[m1], rv1 = rs_s[m1];
        #pragma unroll
        for (int nt = 0; nt < 2; nt++) {
            const float* cc = nt ? c1 : c0;
            int col = r0 + nt * 8 + 2 * (lane & 3);
            float sw0 = sw_s[col], sw1 = sw_s[col + 1];
            float lb0 = lb_s[col], lb1 = lb_s[col + 1];
            float h00 = v0 ? (rv0 * (cc[0] - mu0 * sw0) + lb0) : 0.f;
            float h01 = v0 ? (rv0 * (cc[1] - mu0 * sw1) + lb1) : 0.f;
            float h10 = v1 ? (rv1 * (cc[2] - mu1 * sw0) + lb0) : 0.f;
            float h11 = v1 ? (rv1 * (cc[3] - mu1 * sw1) + lb1) : 0.f;
            *reinterpret_cast<__nv_bfloat162*>(&hl_b[m0 * AB + col]) = f2bf2(h00, h01);
            *reinterpret_cast<__nv_bfloat162*>(&hl_b[m1 * AB + col]) = f2bf2(h10, h11);
        }
    } else {
        const int local = tid - 128;
        const int dq = local & 63;            // d = 4dq .. 4dq+3
        const int jh = local >> 6;
        __half2 acc01 = __float2half2_rn(0.f), acc23 = acc01;
        #pragma unroll
        for (int j4 = 0; j4 < 8; j4++) {
            int j = 32 * jh + 4 * j4;
            uint2 hraw = *reinterpret_cast<const uint2*>(&hid_h[j]);
            __half2 hp01 = *reinterpret_cast<__half2*>(&hraw.x);
            __half2 hp23 = *reinterpret_cast<__half2*>(&hraw.y);
            #pragma unroll
            for (int t = 0; t < 4; t++) {
                unsigned wv = __ldg(reinterpret_cast<const unsigned*>(
                    &g_dn2f8[(j + t) * Dv + 4 * dq]));
                __half hj = (t == 0) ? __low2half(hp01) : (t == 1) ? __high2half(hp01)
                          : (t == 2) ? __low2half(hp23) : __high2half(hp23);
                __half2 hb = __half2half2(hj);
                acc01 = __hfma2(hb, fp8x2_h2(wv), acc01);
                acc23 = __hfma2(hb, fp8x2_h2(wv >> 16), acc23);
            }
        }
        float2 f01 = __half22float2(acc01);
        float2 f23 = __half22float2(acc23);
        *reinterpret_cast<float4*>(&cvsred[jh * Dv + 4 * dq]) =
            make_float4(f01.x, f01.y, f23.x, f23.y);
    }
    __syncthreads();

    // ---- R4: warps 0-3 ph5 MMA (QKVG); warps 4-7 gate finalize + Wu stage
    if (w < 4) {
        const int role = w & 1;      // 0: q&g, 1: k&v
        const int mt = w >> 1;
        const unsigned a_addr = smem_u32(hl_b)
            + (unsigned)(((mt * 16 + (lane & 15)) * AB + ((lane >> 4) << 3)) * 2);
        unsigned a0, a1, a2, a3, a4, a5, a6, a7;
        ldsm_x4(a0, a1, a2, a3, a_addr);
        ldsm_x4(a4, a5, a6, a7, a_addr + 32);
        const int ob1 = role ? 32 : 0;    // k : q
        const int ob2 = role ? 64 : 96;   // v : g
        const unsigned bbase = smem_u32(w4_b) + (unsigned)(((lane & 15) * W4B) * 2);
        const unsigned bk16 = 16 * W4B * 2;
        float c1v[16], c2v[16];
        #pragma unroll
        for (int i = 0; i < 16; i++) { c1v[i] = 0.f; c2v[i] = 0.f; }
        #pragma unroll
        for (int nb = 0; nb < 4; nb++) {
            unsigned b0, b1;
            ldsm_x2t(b0, b1, bbase + (ob1 + nb * 8) * 2);
            mma16816(c1v[4*nb], c1v[4*nb+1], c1v[4*nb+2], c1v[4*nb+3],
                     a0, a1, a2, a3, b0, b1);
            ldsm_x2t(b0, b1, bbase + bk16 + (ob1 + nb * 8) * 2);
            mma16816(c1v[4*nb], c1v[4*nb+1], c1v[4*nb+2], c1v[4*nb+3],
                     a4, a5, a6, a7, b0, b1);
            ldsm_x2t(b0, b1, bbase + (ob2 + nb * 8) * 2);
            mma16816(c2v[4*nb], c2v[4*nb+1], c2v[4*nb+2], c2v[4*nb+3],
                     a0, a1, a2, a3, b0, b1);
            ldsm_x2t(b0, b1, bbase + bk16 + (ob2 + nb * 8) * 2);
            mma16816(c2v[4*nb], c2v[4*nb+1], c2v[4*nb+2], c2v[4*nb+3],
                     a4, a5, a6, a7, b0, b1);
        }
        float qs0 = 0.f, qs1 = 0.f;
        #pragma unroll
        for (int nb = 0; nb < 4; nb++) {
            qs0 += c1v[4*nb] * c1v[4*nb] + c1v[4*nb+1] * c1v[4*nb+1];
            qs1 += c1v[4*nb+2] * c1v[4*nb+2] + c1v[4*nb+3] * c1v[4*nb+3];
        }
        qs0 += __shfl_xor_sync(0xffffffffu, qs0, 1);
        qs0 += __shfl_xor_sync(0xffffffffu, qs0, 2);
        qs1 += __shfl_xor_sync(0xffffffffu, qs1, 1);
        qs1 += __shfl_xor_sync(0xffffffffu, qs1, 2);
        float rn0 = rsqrtf(fmaxf(qs0, 1e-24f));
        float rn1 = rsqrtf(fmaxf(qs1, 1e-24f));
        if (role == 0) {
            const int m0 = mt * 16 + (lane >> 2);
            const int m1 = m0 + 8;
            #pragma unroll
            for (int nb = 0; nb < 4; nb++) {
                int rcol = nb * 8 + 2 * (lane & 3);
                float2 bgv = *reinterpret_cast<const float2*>(&bg_s[rcol]);
                float A0 = c1v[4*nb]   * rn0 * sigm_fast(c2v[4*nb]   + bgv.x);
                float A1 = c1v[4*nb+1] * rn0 * sigm_fast(c2v[4*nb+1] + bgv.y);
                float A2 = c1v[4*nb+2] * rn1 * sigm_fast(c2v[4*nb+2] + bgv.x);
                float A3 = c1v[4*nb+3] * rn1 * sigm_fast(c2v[4*nb+3] + bgv.y);
                *reinterpret_cast<__nv_bfloat162*>(&A_b[m0 * AB + rcol]) = f2bf2(A0, A1);
                *reinterpret_cast<__nv_bfloat162*>(&A_b[m1 * AB + rcol]) = f2bf2(A2, A3);
            }
        } else {
            // gf partials: p[v], v = nb*2 + col; butterfly over hops 4,8,16
            float p[8];
            #pragma unroll
            for (int nb = 0; nb < 4; nb++) {
                p[2*nb]   = c1v[4*nb]   * rn0 * c2v[4*nb]   + c1v[4*nb+2] * rn1 * c2v[4*nb+2];
                p[2*nb+1] = c1v[4*nb+1] * rn0 * c2v[4*nb+1] + c1v[4*nb+3] * rn1 * c2v[4*nb+3];
            }
            #pragma unroll
            for (int i = 0; i < 4; i++) {
                float sent = (lane & 4) ? p[i] : p[i + 4];
                float recv = __shfl_xor_sync(0xffffffffu, sent, 4);
                p[i] = ((lane & 4) ? p[i + 4] : p[i]) + recv;
            }
            #pragma unroll
            for (int i = 0; i < 2; i++) {
                float sent = (lane & 8) ? p[i] : p[i + 2];
                float recv = __shfl_xor_sync(0xffffffffu, sent, 8);
                p[i] = ((lane & 8) ? p[i + 2] : p[i]) + recv;
            }
            {
                float sent = (lane & 16) ? p[0] : p[1];
                float recv = __shfl_xor_sync(0xffffffffu, sent, 16);
                p[0] = ((lane & 16) ? p[1] : p[0]) + recv;
            }
            // v = 4*b4 + 2*b8 + b16 -> nb = 2*b4 + b8, col = b16
            int nb = 2 * ((lane >> 2) & 1) + ((lane >> 3) & 1);
            int col = (lane >> 4) & 1;
            gfp_s[mt * 32 + nb * 8 + 2 * (lane & 3) + col] = p[0];
        }
    } else {
        // gate finalize: 2 d per thread
        const int local = tid - 128;
        const float ev = __ldg(eps_p);
        #pragma unroll
        for (int t = 0; t < 2; t++) {
            int dd = 2 * local + t;
            float dc = (cvsred[dd] + cvsred[Dv + dd]) * FP8SI;
            gate_s[dd] = sigm(__ldg(&g_logits[dd]) + ev * (dc + __ldg(&dn2_b[dd])));
        }
        // cp.async stage Wu into h_b (dead after ph4)
        unsigned wubase = smem_u32(h_b);
        #pragma unroll
        for (int i = 0; i < 8; i++) {
            int idx = local + 128 * i;           // 1024 chunks
            int row = idx >> 5, ch = idx & 31;
            cp_async16(wubase + (unsigned)((row * HB + ch * 8) * 2),
                       g_Wuh + row * Dv + ch * 8);
        }
        cp_commit();
        cp_wait0();
    }
    __syncthreads();   // gfp_s, gate_s, A_b, wu_b all ready

    // ---- R6: ph6 MMA ((A*gf) @ wu_b) -> mixed_b (gf computed inline) -----
    {
        const int mtile = w & 1;
        const int nb0 = (w >> 1) * 64;
        const unsigned a_addr = smem_u32(A_b)
            + (unsigned)(((mtile * 16 + (lane & 15)) * AB + ((lane >> 4) << 3)) * 2);
        unsigned a00, a01, a02, a03, a10, a11, a12, a13;
        ldsm_x4(a00, a01, a02, a03, a_addr);
        ldsm_x4(a10, a11, a12, a13, a_addr + 32);
        {
            int kc2 = 2 * (lane & 3);
            float2 p, q2;
            p = *reinterpret_cast<const float2*>(&gfp_s[kc2]);
            q2 = *reinterpret_cast<const float2*>(&gfp_s[32 + kc2]);
            __nv_bfloat162 s0 = f2bf2(p.x + q2.x, p.y + q2.y);
            p = *reinterpret_cast<const float2*>(&gfp_s[kc2 + 8]);
            q2 = *reinterpret_cast<const float2*>(&gfp_s[40 + kc2]);
            __nv_bfloat162 s1 = f2bf2(p.x + q2.x, p.y + q2.y);
            p = *reinterpret_cast<const float2*>(&gfp_s[kc2 + 16]);
            q2 = *reinterpret_cast<const float2*>(&gfp_s[48 + kc2]);
            __nv_bfloat162 s2 = f2bf2(p.x + q2.x, p.y + q2.y);
            p = *reinterpret_cast<const float2*>(&gfp_s[kc2 + 24]);
            q2 = *reinterpret_cast<const float2*>(&gfp_s[56 + kc2]);
            __nv_bfloat162 s3 = f2bf2(p.x + q2.x, p.y + q2.y);
            __nv_bfloat162* pa;
            pa = reinterpret_cast<__nv_bfloat162*>(&a00); *pa = __hmul2(*pa, s0);
            pa = reinterpret_cast<__nv_bfloat162*>(&a01); *pa = __hmul2(*pa, s0);
            pa = reinterpret_cast<__nv_bfloat162*>(&a02); *pa = __hmul2(*pa, s1);
            pa = reinterpret_cast<__nv_bfloat162*>(&a03); *pa = __hmul2(*pa, s1);
            pa = reinterpret_cast<__nv_bfloat162*>(&a10); *pa = __hmul2(*pa, s2);
            pa = reinterpret_cast<__nv_bfloat162*>(&a11); *pa = __hmul2(*pa, s2);
            pa = reinterpret_cast<__nv_bfloat162*>(&a12); *pa = __hmul2(*pa, s3);
            pa = reinterpret_cast<__nv_bfloat162*>(&a13); *pa = __hmul2(*pa, s3);
        }
        const unsigned b_base = smem_u32(h_b) + (unsigned)(((lane & 15) * HB) * 2);
        const int m0 = mtile * 16 + (lane >> 2);
        const int m1 = m0 + 8;
        #pragma unroll
        for (int t = 0; t < 8; t++) {
            int n0 = nb0 + t * 8;
            unsigned b0, b1, b2, b3;
            ldsm_x2t(b0, b1, b_base + n0 * 2);
            ldsm_x2t(b2, b3, b_base + 16 * HB * 2 + n0 * 2);
            float c0 = 0.f, c1 = 0.f, c2 = 0.f, c3 = 0.f;
            mma16816(c0, c1, c2, c3, a00, a01, a02, a03, b0, b1);
            mma16816(c0, c1, c2, c3, a10, a11, a12, a13, b2, b3);
            int d0 = n0 + 2 * (lane & 3);
            if (m0 < Cv)
                *reinterpret_cast<__nv_bfloat162*>(&mixed_b[m0 * MB + d0]) = f2bf2(c0, c1);
            if (m1 < Cv)
                *reinterpret_cast<__nv_bfloat162*>(&mixed_b[m1 * MB + d0]) = f2bf2(c2, c3);
        }
    }
    __syncthreads();

    // ---- R7: vectorized out = x + gate*(mixed + bu) ----------------------
    {
        const int col0 = 4 * (tid & 63);
        const int rg = tid >> 6;
        float4 gv4 = *reinterpret_cast<const float4*>(&gate_s[col0]);
        float4 bu4 = __ldg(reinterpret_cast<const float4*>(&bu[col0]));
        #pragma unroll
        for (int k = 0; k < 6; k++) {
            int c = rg + 4 * k;
            if (c < Cv) {
                uint2 mm = *reinterpret_cast<const uint2*>(&mixed_b[c * MB + col0]);
                float2 f01 = __bfloat1622float2(*reinterpret_cast<__nv_bfloat162*>(&mm.x));
                float2 f23 = __bfloat1622float2(*reinterpret_cast<__nv_bfloat162*>(&mm.y));
                int gi = xrow + c * PDv + col0;
                float4 xv = *reinterpret_cast<const float4*>(&x[gi]);
                float4 o;
                o.x = xv.x + gv4.x * (f01.x + bu4.x);
                o.y = xv.y + gv4.y * (f01.y + bu4.y);
                o.z = xv.z + gv4.z * (f23.x + bu4.z);
                o.w = xv.w + gv4.w * (f23.y + bu4.w);
                *reinterpret_cast<float4*>(&out[gi]) = o;
            }
        }
    }
}

// ---------------------------------------------------------------------------
extern "C" void kernel_launch(void* const* d_in, const int* in_sizes, int n_in,
                              void* d_out, int out_size) {
    const float* x     = (const float*)d_in[0];
    const float* ln_w  = (const float*)d_in[1];
    const float* ln_b  = (const float*)d_in[2];
    const float* Wd    = (const float*)d_in[3];
    const float* bd    = (const float*)d_in[4];
    const float* Wq    = (const float*)d_in[5];
    const float* Wk    = (const float*)d_in[6];
    const float* Wvp   = (const float*)d_in[7];
    const float* Wg    = (const float*)d_in[8];
    const float* bg    = (const float*)d_in[9];
    const float* Wu    = (const float*)d_in[10];
    const float* bu    = (const float*)d_in[11];
    const float* cn1_w = (const float*)d_in[12];
    const float* cn1_b = (const float*)d_in[13];
    const float* cn2_w = (const float*)d_in[14];
    const float* cn2_b = (const float*)d_in[15];
    const float* dn1_w = (const float*)d_in[16];
    const float* dn1_b = (const float*)d_in[17];
    const float* dn2_w = (const float*)d_in[18];
    const float* dn2_b = (const float*)d_in[19];
    const float* eps   = (const float*)d_in[20];
    float* out = (float*)d_out;

    prep_kernel<<<210, 256>>>(ln_w, ln_b, Wd, bd, Wq, Wk, Wvp, Wg, Wu,
                              cn1_w, cn1_b, cn2_w, cn2_b, dn1_w, dn2_w);
    fused_kernel<<<BPv, 256>>>(x, bg, bu, dn1_b, dn2_b, eps, out);
}